// round 4
// baseline (speedup 1.0000x reference)
#include <cuda_runtime.h>

#define S_LEN   3072
#define EDIM    16
#define NHEAD   5
#define NBATCH  32
#define NCHAIN  (NBATCH * NHEAD)   // 160
#define SPLIT   8
#define SEG_LEN (S_LEN / SPLIT)    // 384
#define CHUNKS  32
#define CLEN    (SEG_LEN / CHUNKS) // 12

typedef unsigned long long ull;

// scratch for params of heads 0..2 (inner): [N][3][S_LEN][E]
__device__ float g_params[(long)NBATCH * 3 * S_LEN * EDIM];
// chunk-prefix scratch, layout per (chain,seg) block: [chunk][c][i] (transposed)
__device__ float g_prefS[(long)NCHAIN * SPLIT * CHUNKS * 256];
__device__ float g_prefZ[(long)NCHAIN * SPLIT * CHUNKS * 16];
__device__ float g_totS [(long)NCHAIN * SPLIT * 256];
__device__ float g_totZ [(long)NCHAIN * SPLIT * 16];

__device__ __forceinline__ float softplus_f(float x) {
    // args here are O(1): no overflow clamp needed
    return __logf(1.0f + __expf(x));
}

// ---- packed fp32x2 helpers (Blackwell) ----
__device__ __forceinline__ ull pk2(float lo, float hi) {
    ull r; asm("mov.b64 %0, {%1, %2};" : "=l"(r) : "f"(lo), "f"(hi)); return r;
}
__device__ __forceinline__ float2 up2(ull a) {
    float2 r; asm("mov.b64 {%0, %1}, %2;" : "=f"(r.x), "=f"(r.y) : "l"(a)); return r;
}
__device__ __forceinline__ ull fma2(ull a, ull b, ull c) {
    ull d; asm("fma.rn.f32x2 %0, %1, %2, %3;" : "=l"(d) : "l"(a), "l"(b), "l"(c)); return d;
}

// ---------------------------------------------------------------------------
// K1: per-chunk sums of k (z) and k v^T (S); exclusive prefix over chunks
// within the segment -> g_prefS/g_prefZ; segment totals -> g_totS/g_totZ.
// grid = 1280 (chain,seg), block = 256 = 32 groups x 8 lanes (2 cols/lane).
// S packed over i-pairs: S0[j] = (S[2j][c0], S[2j+1][c0]), c0 = 2*hl.
// ---------------------------------------------------------------------------
__global__ __launch_bounds__(256, 4) void scan_a(
    const float* __restrict__ x,
    const float* __restrict__ ew,
    const float* __restrict__ eb)
{
    __shared__ __align__(16) float kst[4][CHUNKS][16];
    __shared__ __align__(16) float sS[CHUNKS][16][16];   // [chunk][c][i]
    __shared__ float sZ[CHUNKS][16];

    const int b     = blockIdx.x;
    const int chain = b >> 3, seg = b & 7;
    const int n     = chain / NHEAD, head = chain % NHEAD;
    const int tid   = threadIdx.x;
    const int g     = tid >> 3, hl = tid & 7;

    const float* xw = x + (long)n * S_LEN;
    const long koff = (long)(head + NHEAD)     * S_LEN * EDIM;
    const long voff = (long)(head + 2 * NHEAD) * S_LEN * EDIM;
    const int pos0  = seg * SEG_LEN + g * CLEN;

    const float2* kw = (const float2*)(ew + koff) + (long)pos0 * 8 + hl;
    const float2* kb = (const float2*)(eb + koff) + (long)pos0 * 8 + hl;
    const float2* vw = (const float2*)(ew + voff) + (long)pos0 * 8 + hl;
    const float2* vb = (const float2*)(eb + voff) + (long)pos0 * 8 + hl;

    ull S0[8], S1[8];
#pragma unroll
    for (int j = 0; j < 8; j++) { S0[j] = 0ULL; S1[j] = 0ULL; }
    float z0 = 0.f, z1 = 0.f;

    for (int it = 0; it < CLEN / 2; it++) {
        const int sA = it * 2, sB = sA + 1;
        const int bA = (it & 1) * 2, bB = bA + 1;
        const float xvA = __ldg(xw + pos0 + sA);
        const float xvB = __ldg(xw + pos0 + sB);
        float2 a, c;
        a = __ldg(kw + sA * 8); c = __ldg(kb + sA * 8);
        const float kxA = softplus_f(fmaf(a.x, xvA, c.x));
        const float kyA = softplus_f(fmaf(a.y, xvA, c.y));
        a = __ldg(vw + sA * 8); c = __ldg(vb + sA * 8);
        const float vxA = fmaf(a.x, xvA, c.x);
        const float vyA = fmaf(a.y, xvA, c.y);
        a = __ldg(kw + sB * 8); c = __ldg(kb + sB * 8);
        const float kxB = softplus_f(fmaf(a.x, xvB, c.x));
        const float kyB = softplus_f(fmaf(a.y, xvB, c.y));
        a = __ldg(vw + sB * 8); c = __ldg(vb + sB * 8);
        const float vxB = fmaf(a.x, xvB, c.x);
        const float vyB = fmaf(a.y, xvB, c.y);
        z0 += kxA + kxB; z1 += kyA + kyB;

        *(float2*)&kst[bA][g][2 * hl] = make_float2(kxA, kyA);
        *(float2*)&kst[bB][g][2 * hl] = make_float2(kxB, kyB);
        __syncwarp();

        const ull vxxA = pk2(vxA, vxA), vyyA = pk2(vyA, vyA);
        const ull vxxB = pk2(vxB, vxB), vyyB = pk2(vyB, vyB);
        const ulonglong2* kpA = (const ulonglong2*)kst[bA][g];
        const ulonglong2* kpB = (const ulonglong2*)kst[bB][g];
#pragma unroll
        for (int j4 = 0; j4 < 4; j4++) {
            const ulonglong2 KA = kpA[j4], KB = kpB[j4];
            S0[2*j4]   = fma2(KA.x, vxxA, S0[2*j4]);
            S0[2*j4]   = fma2(KB.x, vxxB, S0[2*j4]);
            S0[2*j4+1] = fma2(KA.y, vxxA, S0[2*j4+1]);
            S0[2*j4+1] = fma2(KB.y, vxxB, S0[2*j4+1]);
            S1[2*j4]   = fma2(KA.x, vyyA, S1[2*j4]);
            S1[2*j4]   = fma2(KB.x, vyyB, S1[2*j4]);
            S1[2*j4+1] = fma2(KA.y, vyyA, S1[2*j4+1]);
            S1[2*j4+1] = fma2(KB.y, vyyB, S1[2*j4+1]);
        }
    }

    // transposed chunk sums -> smem
#pragma unroll
    for (int j = 0; j < 8; j++) {
        *(ull*)&sS[g][2 * hl][2 * j]     = S0[j];
        *(ull*)&sS[g][2 * hl + 1][2 * j] = S1[j];
    }
    *(float2*)&sZ[g][2 * hl] = make_float2(z0, z1);
    __syncthreads();

    // serial exclusive scan over chunks (coalesced stores)
    {
        float run = 0.f;
        const long base = (long)b * CHUNKS * 256 + tid;
        const int c = tid >> 4, i = tid & 15;
        for (int gg = 0; gg < CHUNKS; gg++) {
            g_prefS[base + gg * 256] = run;
            run += sS[gg][c][i];
        }
        g_totS[(long)b * 256 + tid] = run;
    }
    if (tid < 16) {
        float rz = 0.f;
        const long bz = (long)b * CHUNKS * 16 + tid;
        for (int gg = 0; gg < CHUNKS; gg++) {
            g_prefZ[bz + gg * 16] = rz;
            rz += sZ[gg][tid];
        }
        g_totZ[b * 16 + tid] = rz;
    }
}

// ---------------------------------------------------------------------------
// K2: exclusive prefix of segment totals across the 8 segments of each chain
// (in place). grid = 160, block = 288.
// ---------------------------------------------------------------------------
__global__ void scan_b()
{
    const int chain = blockIdx.x;
    const int t = threadIdx.x;
    if (t < 256) {
        float run = 0.f;
        for (int s = 0; s < SPLIT; s++) {
            const long idx = ((long)chain * SPLIT + s) * 256 + t;
            const float v = g_totS[idx]; g_totS[idx] = run; run += v;
        }
    } else if (t < 272) {
        const int i = t - 256;
        float run = 0.f;
        for (int s = 0; s < SPLIT; s++) {
            const long idx = ((long)chain * SPLIT + s) * 16 + i;
            const float v = g_totZ[idx]; g_totZ[idx] = run; run += v;
        }
    }
}

// ---------------------------------------------------------------------------
// K3: rescan each chunk from prefix state with q; emit params (heads 0-2 ->
// scratch) or e-summed shifted outputs (heads 3-4 -> d_out).
// ---------------------------------------------------------------------------
__global__ __launch_bounds__(256, 3) void scan_c(
    const float* __restrict__ x,
    const float* __restrict__ ew,
    const float* __restrict__ eb,
    const float* __restrict__ ind_out_b,
    const float* __restrict__ ind_res_w,
    float* __restrict__ out)
{
    __shared__ __align__(16) float st[4][CHUNKS][32];  // [buf][grp][k:0..15|q:16..31]

    const int b     = blockIdx.x;
    const int chain = b >> 3, seg = b & 7;
    const int n     = chain / NHEAD, head = chain % NHEAD;
    const int tid   = threadIdx.x;
    const int g     = tid >> 3, hl = tid & 7;

    const float* xw = x + (long)n * S_LEN;
    const long qoff = (long)(head)             * S_LEN * EDIM;
    const long koff = (long)(head + NHEAD)     * S_LEN * EDIM;
    const long voff = (long)(head + 2 * NHEAD) * S_LEN * EDIM;
    const int pos0  = seg * SEG_LEN + g * CLEN;

    // prefix state: chunk prefix + segment exclusive total
    ull S0[8], S1[8];
    float z0, z1;
    {
        const ull ONE = pk2(1.f, 1.f);
        const ulonglong2* pp = (const ulonglong2*)(g_prefS + ((long)b * CHUNKS + g) * 256);
        const ulonglong2* tp = (const ulonglong2*)(g_totS + ((long)chain * SPLIT + seg) * 256);
        const int r0 = (2 * hl) * 4, r1 = (2 * hl + 1) * 4;
#pragma unroll
        for (int j2 = 0; j2 < 4; j2++) {
            const ulonglong2 pv = pp[r0 + j2], tv = tp[r0 + j2];
            S0[2*j2]   = fma2(ONE, tv.x, pv.x);
            S0[2*j2+1] = fma2(ONE, tv.y, pv.y);
        }
#pragma unroll
        for (int j2 = 0; j2 < 4; j2++) {
            const ulonglong2 pv = pp[r1 + j2], tv = tp[r1 + j2];
            S1[2*j2]   = fma2(ONE, tv.x, pv.x);
            S1[2*j2+1] = fma2(ONE, tv.y, pv.y);
        }
        const float2 zz = *(const float2*)&g_prefZ[((long)b * CHUNKS + g) * 16 + 2 * hl];
        const float2 zt = *(const float2*)&g_totZ[((long)chain * SPLIT + seg) * 16 + 2 * hl];
        z0 = zz.x + zt.x; z1 = zz.y + zt.y;
    }

    const bool isInner = (head < 3);
    float* pdst = nullptr;
    float* odst = nullptr;
    if (isInner) {
        pdst = g_params + ((long)(n * 3 + head) * S_LEN) * EDIM;
    } else {
        const long base = (long)3 * NBATCH * S_LEN * EDIM
                        + (long)(head - 3) * NBATCH * S_LEN;
        odst = out + base + (long)n * S_LEN;
        if (tid == 0 && seg == 0)
            odst[0] = (head == 3) ? ind_out_b[0] : ind_res_w[0];
    }

    const float2* qw = (const float2*)(ew + qoff) + (long)pos0 * 8 + hl;
    const float2* qb = (const float2*)(eb + qoff) + (long)pos0 * 8 + hl;
    const float2* kw = (const float2*)(ew + koff) + (long)pos0 * 8 + hl;
    const float2* kb = (const float2*)(eb + koff) + (long)pos0 * 8 + hl;
    const float2* vw = (const float2*)(ew + voff) + (long)pos0 * 8 + hl;
    const float2* vb = (const float2*)(eb + voff) + (long)pos0 * 8 + hl;

    for (int it = 0; it < CLEN / 2; it++) {
        const int sA = it * 2, sB = sA + 1;
        const int posA = pos0 + sA, posB = posA + 1;
        const int bA = (it & 1) * 2, bB = bA + 1;
        float2 a, c;
        const float xvA = __ldg(xw + posA), xvB = __ldg(xw + posB);
        a = __ldg(qw + sA * 8); c = __ldg(qb + sA * 8);
        const float qxA = softplus_f(fmaf(a.x, xvA, c.x));
        const float qyA = softplus_f(fmaf(a.y, xvA, c.y));
        a = __ldg(kw + sA * 8); c = __ldg(kb + sA * 8);
        const float kxA = softplus_f(fmaf(a.x, xvA, c.x));
        const float kyA = softplus_f(fmaf(a.y, xvA, c.y));
        a = __ldg(vw + sA * 8); c = __ldg(vb + sA * 8);
        const float vxA = fmaf(a.x, xvA, c.x);
        const float vyA = fmaf(a.y, xvA, c.y);
        a = __ldg(qw + sB * 8); c = __ldg(qb + sB * 8);
        const float qxB = softplus_f(fmaf(a.x, xvB, c.x));
        const float qyB = softplus_f(fmaf(a.y, xvB, c.y));
        a = __ldg(kw + sB * 8); c = __ldg(kb + sB * 8);
        const float kxB = softplus_f(fmaf(a.x, xvB, c.x));
        const float kyB = softplus_f(fmaf(a.y, xvB, c.y));
        a = __ldg(vw + sB * 8); c = __ldg(vb + sB * 8);
        const float vxB = fmaf(a.x, xvB, c.x);
        const float vyB = fmaf(a.y, xvB, c.y);

        const float zA0 = z0 + kxA, zA1 = z1 + kyA;
        const float zB0 = zA0 + kxB, zB1 = zA1 + kyB;
        z0 = zB0; z1 = zB1;

        *(float2*)&st[bA][g][2 * hl]      = make_float2(kxA, kyA);
        *(float2*)&st[bA][g][16 + 2 * hl] = make_float2(qxA, qyA);
        *(float2*)&st[bB][g][2 * hl]      = make_float2(kxB, kyB);
        *(float2*)&st[bB][g][16 + 2 * hl] = make_float2(qxB, qyB);
        __syncwarp();

        // ---- step A ----
        {
            float dp = fmaf(qxA, zA0, qyA * zA1);
            dp += __shfl_xor_sync(0xffffffffu, dp, 1, 8);
            dp += __shfl_xor_sync(0xffffffffu, dp, 2, 8);
            dp += __shfl_xor_sync(0xffffffffu, dp, 4, 8);
            const ull vxx = pk2(vxA, vxA), vyy = pk2(vyA, vyA);
            const ulonglong2* kp = (const ulonglong2*)&st[bA][g][0];
            const ulonglong2* qp = (const ulonglong2*)&st[bA][g][16];
            ull n0 = 0ULL, n1 = 0ULL;
#pragma unroll
            for (int j4 = 0; j4 < 4; j4++) {
                const ulonglong2 K = kp[j4], Q = qp[j4];
                S0[2*j4]   = fma2(K.x, vxx, S0[2*j4]);   n0 = fma2(Q.x, S0[2*j4],   n0);
                S0[2*j4+1] = fma2(K.y, vxx, S0[2*j4+1]); n0 = fma2(Q.y, S0[2*j4+1], n0);
                S1[2*j4]   = fma2(K.x, vyy, S1[2*j4]);   n1 = fma2(Q.x, S1[2*j4],   n1);
                S1[2*j4+1] = fma2(K.y, vyy, S1[2*j4+1]); n1 = fma2(Q.y, S1[2*j4+1], n1);
            }
            const float r = __fdividef(1.0f, dp);
            const float2 u0 = up2(n0), u1 = up2(n1);
            const float p0 = (u0.x + u0.y) * r, p1 = (u1.x + u1.y) * r;
            if (isInner) {
                *(float2*)&pdst[(long)posA * EDIM + 2 * hl] = make_float2(p0, p1);
            } else {
                float tot = p0 + p1;
                tot += __shfl_xor_sync(0xffffffffu, tot, 1, 8);
                tot += __shfl_xor_sync(0xffffffffu, tot, 2, 8);
                tot += __shfl_xor_sync(0xffffffffu, tot, 4, 8);
                if (hl == 0 && posA + 1 < S_LEN) odst[posA + 1] = tot;
            }
        }
        // ---- step B ----
        {
            float dp = fmaf(qxB, zB0, qyB * zB1);
            dp += __shfl_xor_sync(0xffffffffu, dp, 1, 8);
            dp += __shfl_xor_sync(0xffffffffu, dp, 2, 8);
            dp += __shfl_xor_sync(0xffffffffu, dp, 4, 8);
            const ull vxx = pk2(vxB, vxB), vyy = pk2(vyB, vyB);
            const ulonglong2* kp = (const ulonglong2*)&st[bB][g][0];
            const ulonglong2* qp = (const ulonglong2*)&st[bB][g][16];
            ull n0 = 0ULL, n1 = 0ULL;
#pragma unroll
            for (int j4 = 0; j4 < 4; j4++) {
                const ulonglong2 K = kp[j4], Q = qp[j4];
                S0[2*j4]   = fma2(K.x, vxx, S0[2*j4]);   n0 = fma2(Q.x, S0[2*j4],   n0);
                S0[2*j4+1] = fma2(K.y, vxx, S0[2*j4+1]); n0 = fma2(Q.y, S0[2*j4+1], n0);
                S1[2*j4]   = fma2(K.x, vyy, S1[2*j4]);   n1 = fma2(Q.x, S1[2*j4],   n1);
                S1[2*j4+1] = fma2(K.y, vyy, S1[2*j4+1]); n1 = fma2(Q.y, S1[2*j4+1], n1);
            }
            const float r = __fdividef(1.0f, dp);
            const float2 u0 = up2(n0), u1 = up2(n1);
            const float p0 = (u0.x + u0.y) * r, p1 = (u1.x + u1.y) * r;
            if (isInner) {
                *(float2*)&pdst[(long)posB * EDIM + 2 * hl] = make_float2(p0, p1);
            } else {
                float tot = p0 + p1;
                tot += __shfl_xor_sync(0xffffffffu, tot, 1, 8);
                tot += __shfl_xor_sync(0xffffffffu, tot, 2, 8);
                tot += __shfl_xor_sync(0xffffffffu, tot, 4, 8);
                if (hl == 0 && posB + 1 < S_LEN) odst[posB + 1] = tot;
            }
        }
    }
}

// ---------------------------------------------------------------------------
// K4: per-position MLP for heads 0..2 on shifted params (fp32x2 packed).
// ---------------------------------------------------------------------------
__global__ __launch_bounds__(256, 4) void mlp_kernel(
    const float* __restrict__ ind_in_w,
    const float* __restrict__ ind_in_b,
    const float* __restrict__ ind_out_w,
    const float* __restrict__ fc1_w,
    const float* __restrict__ fc1_b,
    const float* __restrict__ fc2_w,
    const float* __restrict__ fc2_b,
    float* __restrict__ out)
{
    __shared__ __align__(16) float w1[32 * 16];
    __shared__ __align__(16) float w2t[32][16];   // transposed: [o][e]
    __shared__ float b1[32];
    __shared__ __align__(16) float b2[16];

    const int tid = threadIdx.x;
    for (int i = tid; i < 512; i += 256) w1[i] = fc1_w[i];
    for (int i = tid; i < 512; i += 256) {
        const int p = i >> 5, o = i & 31;   // fc2_w is [E][2E] row-major
        w2t[o][p] = fc2_w[i];
    }
    if (tid < 32) b1[tid] = fc1_b[tid];
    if (tid < 16) b2[tid] = fc2_b[tid];
    __syncthreads();

    const int t   = blockIdx.x * 256 + tid;
    const int n   = t / (3 * S_LEN);
    const int r   = t - n * (3 * S_LEN);
    const int tt  = r / S_LEN;
    const int pos = r - tt * S_LEN;

    ull pp[8];
    if (pos == 0) {
        float p[16];
#pragma unroll
        for (int e = 0; e < 16; e++) {
            p[e] = (tt == 0) ? softplus_f(ind_in_w[e])
                 : (tt == 1) ? ind_in_b[e]
                             : ind_out_w[e];
        }
#pragma unroll
        for (int j = 0; j < 8; j++) pp[j] = pk2(p[2*j], p[2*j+1]);
    } else {
        const ulonglong2* src = (const ulonglong2*)(g_params
            + ((long)(n * 3 + tt) * S_LEN + (pos - 1)) * EDIM);
        const ulonglong2 A = src[0], B = src[1], C = src[2], D = src[3];
        pp[0]=A.x; pp[1]=A.y; pp[2]=B.x; pp[3]=B.y;
        pp[4]=C.x; pp[5]=C.y; pp[6]=D.x; pp[7]=D.y;
    }

    ull acc[8];
#pragma unroll
    for (int j = 0; j < 8; j++) acc[j] = *(const ull*)&b2[2 * j];

#pragma unroll
    for (int o = 0; o < 32; o++) {
        const ulonglong2* w1p = (const ulonglong2*)&w1[o * 16];
        const ulonglong2 W0 = w1p[0], W1 = w1p[1], W2 = w1p[2], W3 = w1p[3];
        ull ha = 0ULL, hb = 0ULL;
        ha = fma2(pp[0], W0.x, ha); hb = fma2(pp[1], W0.y, hb);
        ha = fma2(pp[2], W1.x, ha); hb = fma2(pp[3], W1.y, hb);
        ha = fma2(pp[4], W2.x, ha); hb = fma2(pp[5], W2.y, hb);
        ha = fma2(pp[6], W3.x, ha); hb = fma2(pp[7], W3.y, hb);
        const float2 ua = up2(ha), ub = up2(hb);
        const float hs = fmaxf(ua.x + ua.y + ub.x + ub.y + b1[o], 0.0f);
        const ull hp = pk2(hs, hs);
        const ulonglong2* w2p = (const ulonglong2*)&w2t[o][0];
        const ulonglong2 V0 = w2p[0], V1 = w2p[1], V2 = w2p[2], V3 = w2p[3];
        acc[0] = fma2(hp, V0.x, acc[0]); acc[1] = fma2(hp, V0.y, acc[1]);
        acc[2] = fma2(hp, V1.x, acc[2]); acc[3] = fma2(hp, V1.y, acc[3]);
        acc[4] = fma2(hp, V2.x, acc[4]); acc[5] = fma2(hp, V2.y, acc[5]);
        acc[6] = fma2(hp, V3.x, acc[6]); acc[7] = fma2(hp, V3.y, acc[7]);
    }

    if (tt == 0) {   // in_proj_weight gets a final softplus
#pragma unroll
        for (int j = 0; j < 8; j++) {
            const float2 u = up2(acc[j]);
            acc[j] = pk2(softplus_f(u.x), softplus_f(u.y));
        }
    }

    ulonglong2* dst = (ulonglong2*)(out
        + ((long)tt * NBATCH * S_LEN + (long)n * S_LEN + pos) * EDIM);
    ulonglong2 o0, o1;
    o0.x = acc[0]; o0.y = acc[1]; dst[0] = o0;
    o1.x = acc[2]; o1.y = acc[3]; dst[1] = o1;
    o0.x = acc[4]; o0.y = acc[5]; dst[2] = o0;
    o1.x = acc[6]; o1.y = acc[7]; dst[3] = o1;
}

// ---------------------------------------------------------------------------
extern "C" void kernel_launch(void* const* d_in, const int* in_sizes, int n_in,
                              void* d_out, int out_size)
{
    const float* x         = (const float*)d_in[0];
    const float* ew        = (const float*)d_in[1];
    const float* eb        = (const float*)d_in[2];
    const float* ind_in_w  = (const float*)d_in[3];
    const float* ind_in_b  = (const float*)d_in[4];
    const float* ind_out_w = (const float*)d_in[5];
    const float* ind_out_b = (const float*)d_in[6];
    const float* ind_res_w = (const float*)d_in[7];
    const float* fc1_w     = (const float*)d_in[8];
    const float* fc1_b     = (const float*)d_in[9];
    const float* fc2_w     = (const float*)d_in[10];
    const float* fc2_b     = (const float*)d_in[11];
    float* out = (float*)d_out;

    scan_a<<<NCHAIN * SPLIT, 256>>>(x, ew, eb);
    scan_b<<<NCHAIN, 288>>>();
    scan_c<<<NCHAIN * SPLIT, 256>>>(x, ew, eb, ind_out_b, ind_res_w, out);
    mlp_kernel<<<(NBATCH * 3 * S_LEN) / 256, 256>>>(
        ind_in_w, ind_in_b, ind_out_w, fc1_w, fc1_b, fc2_w, fc2_b, out);
}

// round 5
// speedup vs baseline: 1.1394x; 1.1394x over previous
#include <cuda_runtime.h>

#define S_LEN   3072
#define EDIM    16
#define NHEAD   5
#define NBATCH  32
#define NCHAIN  (NBATCH * NHEAD)   // 160
#define SPLIT   2
#define SEG_LEN (S_LEN / SPLIT)    // 1536
#define CHUNKS  32
#define CLEN    (SEG_LEN / CHUNKS) // 48

// scratch for params of heads 0..2 (inner): [N][3][S_LEN][E]
__device__ float g_params[(long)NBATCH * 3 * S_LEN * EDIM];
// chunk-prefix scratch: per (chain,seg) block: 32 chunks x 256 S-entries / 16 z
__device__ float g_prefS[(long)NCHAIN * SPLIT * CHUNKS * 256];
__device__ float g_prefZ[(long)NCHAIN * SPLIT * CHUNKS * 16];
__device__ float g_totS [(long)NCHAIN * SPLIT * 256];
__device__ float g_totZ [(long)NCHAIN * SPLIT * 16];

__device__ __forceinline__ float softplus_f(float x) {
    return fmaxf(x, 0.0f) + __logf(1.0f + __expf(-fabsf(x)));
}

// ---------------------------------------------------------------------------
// K1: per-chunk sums of k (z) and k v^T (S), exclusive prefix within segment,
// prefixes + segment totals -> global scratch.   (verbatim from the measured
// 28.9us version: grid=320, block=256 = 32 groups x 8 lanes, 2 cols/lane)
// ---------------------------------------------------------------------------
__global__ __launch_bounds__(256, 4) void scan_a(
    const float* __restrict__ x,
    const float* __restrict__ ew,
    const float* __restrict__ eb)
{
    __shared__ __align__(16) float kst[2][CHUNKS][16];
    __shared__ float sS[CHUNKS][16][16];
    __shared__ float sZ[CHUNKS][16];

    const int b     = blockIdx.x;
    const int chain = b / SPLIT, seg = b % SPLIT;
    const int n     = chain / NHEAD, head = chain % NHEAD;
    const int tid   = threadIdx.x;
    const int g     = tid >> 3, hl = tid & 7;

    const float* xw = x + (long)n * S_LEN;
    const long koff = (long)(head + NHEAD)     * S_LEN * EDIM;
    const long voff = (long)(head + 2 * NHEAD) * S_LEN * EDIM;
    const int pos0  = seg * SEG_LEN + g * CLEN;

    const float2* kw = (const float2*)(ew + koff) + (long)pos0 * 8 + hl;
    const float2* kb = (const float2*)(eb + koff) + (long)pos0 * 8 + hl;
    const float2* vw = (const float2*)(ew + voff) + (long)pos0 * 8 + hl;
    const float2* vb = (const float2*)(eb + voff) + (long)pos0 * 8 + hl;

    float S0[16], S1[16];
#pragma unroll
    for (int i = 0; i < 16; i++) { S0[i] = 0.f; S1[i] = 0.f; }
    float z0 = 0.f, z1 = 0.f;

    for (int s = 0; s < CLEN; s++) {
        const float xv = __ldg(xw + pos0 + s);
        const float2 a  = __ldg(kw + s * 8);
        const float2 bb = __ldg(kb + s * 8);
        const float kx = softplus_f(fmaf(a.x, xv, bb.x));
        const float ky = softplus_f(fmaf(a.y, xv, bb.y));
        const float2 c  = __ldg(vw + s * 8);
        const float2 d  = __ldg(vb + s * 8);
        const float vx = fmaf(c.x, xv, d.x);
        const float vy = fmaf(c.y, xv, d.y);
        z0 += kx; z1 += ky;

        const int buf = s & 1;
        *(float2*)&kst[buf][g][2 * hl] = make_float2(kx, ky);
        __syncwarp();
        const float4* kv = (const float4*)kst[buf][g];
        const float4 K0 = kv[0], K1 = kv[1], K2 = kv[2], K3 = kv[3];
        const float kk[16] = {K0.x,K0.y,K0.z,K0.w, K1.x,K1.y,K1.z,K1.w,
                              K2.x,K2.y,K2.z,K2.w, K3.x,K3.y,K3.z,K3.w};
#pragma unroll
        for (int i = 0; i < 16; i++) {
            S0[i] = fmaf(kk[i], vx, S0[i]);
            S1[i] = fmaf(kk[i], vy, S1[i]);
        }
    }

#pragma unroll
    for (int i = 0; i < 16; i++)
        *(float2*)&sS[g][i][2 * hl] = make_float2(S0[i], S1[i]);
    *(float2*)&sZ[g][2 * hl] = make_float2(z0, z1);
    __syncthreads();

    // serial exclusive scan over chunks; 256 S entries (+16 z on tid<16)
    {
        const int i = tid >> 4, c = tid & 15;
        float run = 0.f;
        const long base = ((long)b * CHUNKS) * 256 + tid;
        for (int gg = 0; gg < CHUNKS; gg++) {
            g_prefS[base + gg * 256] = run;
            run += sS[gg][i][c];
        }
        g_totS[(long)b * 256 + tid] = run;
        if (tid < 16) {
            float rz = 0.f;
            const long bz = ((long)b * CHUNKS) * 16 + tid;
            for (int gg = 0; gg < CHUNKS; gg++) {
                g_prefZ[bz + gg * 16] = rz;
                rz += sZ[gg][tid];
            }
            g_totZ[b * 16 + tid] = rz;
        }
    }
}

// ---------------------------------------------------------------------------
// K2: rescan each chunk from its prefix state with q; emit params
// (heads 0-2 -> scratch) or e-summed shifted outputs (heads 3-4 -> d_out).
// Scalar math, 2-position unroll, 4 rotating broadcast buffers,
// one __syncwarp per 2 positions.
// ---------------------------------------------------------------------------
__global__ __launch_bounds__(256, 3) void scan_c(
    const float* __restrict__ x,
    const float* __restrict__ ew,
    const float* __restrict__ eb,
    const float* __restrict__ ind_out_b,
    const float* __restrict__ ind_res_w,
    float* __restrict__ out)
{
    __shared__ __align__(16) float st[4][CHUNKS][32];  // [buf][grp][k:0..15|q:16..31]

    const int b     = blockIdx.x;
    const int chain = b / SPLIT, seg = b % SPLIT;
    const int n     = chain / NHEAD, head = chain % NHEAD;
    const int tid   = threadIdx.x;
    const int g     = tid >> 3, hl = tid & 7;

    const float* xw = x + (long)n * S_LEN;
    const long qoff = (long)(head)             * S_LEN * EDIM;
    const long koff = (long)(head + NHEAD)     * S_LEN * EDIM;
    const long voff = (long)(head + 2 * NHEAD) * S_LEN * EDIM;
    const int pos0  = seg * SEG_LEN + g * CLEN;

    // load prefix state (chunk prefix; seg==1 adds segment-0 totals)
    float S0[16], S1[16], z0, z1;
    {
        const long pb = ((long)b * CHUNKS + g) * 256;
#pragma unroll
        for (int i = 0; i < 16; i++) {
            const float2 t = *(const float2*)&g_prefS[pb + i * 16 + 2 * hl];
            S0[i] = t.x; S1[i] = t.y;
        }
        const float2 tz = *(const float2*)&g_prefZ[((long)b * CHUNKS + g) * 16 + 2 * hl];
        z0 = tz.x; z1 = tz.y;
        if (seg) {
            const long tb = (long)(chain * SPLIT) * 256;
#pragma unroll
            for (int i = 0; i < 16; i++) {
                const float2 t = *(const float2*)&g_totS[tb + i * 16 + 2 * hl];
                S0[i] += t.x; S1[i] += t.y;
            }
            const float2 t = *(const float2*)&g_totZ[(chain * SPLIT) * 16 + 2 * hl];
            z0 += t.x; z1 += t.y;
        }
    }

    const bool isInner = (head < 3);
    float* pdst = nullptr;
    float* odst = nullptr;
    if (isInner) {
        pdst = g_params + ((long)(n * 3 + head) * S_LEN) * EDIM;
    } else {
        const long base = (long)3 * NBATCH * S_LEN * EDIM
                        + (long)(head - 3) * NBATCH * S_LEN;
        odst = out + base + (long)n * S_LEN;
        if (tid == 0 && seg == 0)
            odst[0] = (head == 3) ? ind_out_b[0] : ind_res_w[0];
    }

    const float2* qw = (const float2*)(ew + qoff) + (long)pos0 * 8 + hl;
    const float2* qb = (const float2*)(eb + qoff) + (long)pos0 * 8 + hl;
    const float2* kw = (const float2*)(ew + koff) + (long)pos0 * 8 + hl;
    const float2* kb = (const float2*)(eb + koff) + (long)pos0 * 8 + hl;
    const float2* vw = (const float2*)(ew + voff) + (long)pos0 * 8 + hl;
    const float2* vb = (const float2*)(eb + voff) + (long)pos0 * 8 + hl;

    for (int it = 0; it < CLEN / 2; it++) {
        const int sA = it * 2, sB = sA + 1;
        const int posA = pos0 + sA, posB = posA + 1;
        const int bA = (it & 1) * 2, bB = bA + 1;
        float2 a, c;
        const float xvA = __ldg(xw + posA), xvB = __ldg(xw + posB);
        a = __ldg(qw + sA * 8); c = __ldg(qb + sA * 8);
        const float qxA = softplus_f(fmaf(a.x, xvA, c.x));
        const float qyA = softplus_f(fmaf(a.y, xvA, c.y));
        a = __ldg(kw + sA * 8); c = __ldg(kb + sA * 8);
        const float kxA = softplus_f(fmaf(a.x, xvA, c.x));
        const float kyA = softplus_f(fmaf(a.y, xvA, c.y));
        a = __ldg(vw + sA * 8); c = __ldg(vb + sA * 8);
        const float vxA = fmaf(a.x, xvA, c.x);
        const float vyA = fmaf(a.y, xvA, c.y);
        a = __ldg(qw + sB * 8); c = __ldg(qb + sB * 8);
        const float qxB = softplus_f(fmaf(a.x, xvB, c.x));
        const float qyB = softplus_f(fmaf(a.y, xvB, c.y));
        a = __ldg(kw + sB * 8); c = __ldg(kb + sB * 8);
        const float kxB = softplus_f(fmaf(a.x, xvB, c.x));
        const float kyB = softplus_f(fmaf(a.y, xvB, c.y));
        a = __ldg(vw + sB * 8); c = __ldg(vb + sB * 8);
        const float vxB = fmaf(a.x, xvB, c.x);
        const float vyB = fmaf(a.y, xvB, c.y);

        const float zA0 = z0 + kxA, zA1 = z1 + kyA;
        const float zB0 = zA0 + kxB, zB1 = zA1 + kyB;
        z0 = zB0; z1 = zB1;

        *(float2*)&st[bA][g][2 * hl]      = make_float2(kxA, kyA);
        *(float2*)&st[bA][g][16 + 2 * hl] = make_float2(qxA, qyA);
        *(float2*)&st[bB][g][2 * hl]      = make_float2(kxB, kyB);
        *(float2*)&st[bB][g][16 + 2 * hl] = make_float2(qxB, qyB);
        __syncwarp();

        // both dp chains start immediately (independent), overlapping shfl lat
        float dpA = fmaf(qxA, zA0, qyA * zA1);
        float dpB = fmaf(qxB, zB0, qyB * zB1);
        dpA += __shfl_xor_sync(0xffffffffu, dpA, 1, 8);
        dpB += __shfl_xor_sync(0xffffffffu, dpB, 1, 8);
        dpA += __shfl_xor_sync(0xffffffffu, dpA, 2, 8);
        dpB += __shfl_xor_sync(0xffffffffu, dpB, 2, 8);
        dpA += __shfl_xor_sync(0xffffffffu, dpA, 4, 8);
        dpB += __shfl_xor_sync(0xffffffffu, dpB, 4, 8);

        // ---- step A ----
        float p0A, p1A;
        {
            const float4* kv = (const float4*)&st[bA][g][0];
            const float4* qv = (const float4*)&st[bA][g][16];
            float num0 = 0.f, num1 = 0.f;
#pragma unroll
            for (int q4 = 0; q4 < 4; q4++) {
                const float4 K = kv[q4];
                const float4 Q = qv[q4];
                S0[4*q4+0] = fmaf(K.x, vxA, S0[4*q4+0]); num0 = fmaf(Q.x, S0[4*q4+0], num0);
                S0[4*q4+1] = fmaf(K.y, vxA, S0[4*q4+1]); num0 = fmaf(Q.y, S0[4*q4+1], num0);
                S0[4*q4+2] = fmaf(K.z, vxA, S0[4*q4+2]); num0 = fmaf(Q.z, S0[4*q4+2], num0);
                S0[4*q4+3] = fmaf(K.w, vxA, S0[4*q4+3]); num0 = fmaf(Q.w, S0[4*q4+3], num0);
                S1[4*q4+0] = fmaf(K.x, vyA, S1[4*q4+0]); num1 = fmaf(Q.x, S1[4*q4+0], num1);
                S1[4*q4+1] = fmaf(K.y, vyA, S1[4*q4+1]); num1 = fmaf(Q.y, S1[4*q4+1], num1);
                S1[4*q4+2] = fmaf(K.z, vyA, S1[4*q4+2]); num1 = fmaf(Q.z, S1[4*q4+2], num1);
                S1[4*q4+3] = fmaf(K.w, vyA, S1[4*q4+3]); num1 = fmaf(Q.w, S1[4*q4+3], num1);
            }
            const float r = __fdividef(1.0f, dpA);
            p0A = num0 * r; p1A = num1 * r;
        }
        // ---- step B ----
        float p0B, p1B;
        {
            const float4* kv = (const float4*)&st[bB][g][0];
            const float4* qv = (const float4*)&st[bB][g][16];
            float num0 = 0.f, num1 = 0.f;
#pragma unroll
            for (int q4 = 0; q4 < 4; q4++) {
                const float4 K = kv[q4];
                const float4 Q = qv[q4];
                S0[4*q4+0] = fmaf(K.x, vxB, S0[4*q4+0]); num0 = fmaf(Q.x, S0[4*q4+0], num0);
                S0[4*q4+1] = fmaf(K.y, vxB, S0[4*q4+1]); num0 = fmaf(Q.y, S0[4*q4+1], num0);
                S0[4*q4+2] = fmaf(K.z, vxB, S0[4*q4+2]); num0 = fmaf(Q.z, S0[4*q4+2], num0);
                S0[4*q4+3] = fmaf(K.w, vxB, S0[4*q4+3]); num0 = fmaf(Q.w, S0[4*q4+3], num0);
                S1[4*q4+0] = fmaf(K.x, vyB, S1[4*q4+0]); num1 = fmaf(Q.x, S1[4*q4+0], num1);
                S1[4*q4+1] = fmaf(K.y, vyB, S1[4*q4+1]); num1 = fmaf(Q.y, S1[4*q4+1], num1);
                S1[4*q4+2] = fmaf(K.z, vyB, S1[4*q4+2]); num1 = fmaf(Q.z, S1[4*q4+2], num1);
                S1[4*q4+3] = fmaf(K.w, vyB, S1[4*q4+3]); num1 = fmaf(Q.w, S1[4*q4+3], num1);
            }
            const float r = __fdividef(1.0f, dpB);
            p0B = num0 * r; p1B = num1 * r;
        }

        if (isInner) {
            *(float2*)&pdst[(long)posA * EDIM + 2 * hl] = make_float2(p0A, p1A);
            *(float2*)&pdst[(long)posB * EDIM + 2 * hl] = make_float2(p0B, p1B);
        } else {
            float totA = p0A + p1A;
            float totB = p0B + p1B;
            totA += __shfl_xor_sync(0xffffffffu, totA, 1, 8);
            totB += __shfl_xor_sync(0xffffffffu, totB, 1, 8);
            totA += __shfl_xor_sync(0xffffffffu, totA, 2, 8);
            totB += __shfl_xor_sync(0xffffffffu, totB, 2, 8);
            totA += __shfl_xor_sync(0xffffffffu, totA, 4, 8);
            totB += __shfl_xor_sync(0xffffffffu, totB, 4, 8);
            if (hl == 0) {
                odst[posA + 1] = totA;
                if (posB + 1 < S_LEN) odst[posB + 1] = totB;
            }
        }
    }
}

// ---------------------------------------------------------------------------
// K3: per-position MLP for heads 0..2 on shifted params.
// 2 positions per thread (pos, pos+1536) sharing every weight load.
// ---------------------------------------------------------------------------
__global__ __launch_bounds__(128) void mlp_kernel(
    const float* __restrict__ ind_in_w,
    const float* __restrict__ ind_in_b,
    const float* __restrict__ ind_out_w,
    const float* __restrict__ fc1_w,
    const float* __restrict__ fc1_b,
    const float* __restrict__ fc2_w,
    const float* __restrict__ fc2_b,
    float* __restrict__ out)
{
    __shared__ __align__(16) float w1[32 * 16];
    __shared__ __align__(16) float w2t[32][16];   // transposed: [o][e]
    __shared__ float b1[32];
    __shared__ float b2[16];

    const int tid = threadIdx.x;
    for (int i = tid; i < 512; i += 128) w1[i] = fc1_w[i];
    for (int i = tid; i < 512; i += 128) {
        const int p = i >> 5, o = i & 31;   // fc2_w is [E][2E] row-major
        w2t[o][p] = fc2_w[i];
    }
    if (tid < 32) b1[tid] = fc1_b[tid];
    if (tid < 16) b2[tid] = fc2_b[tid];
    __syncthreads();

    const int HALF = S_LEN / 2;                  // 1536
    const int t    = blockIdx.x * 128 + tid;     // 0 .. 147455
    const int n    = t / (3 * HALF);
    const int r    = t - n * (3 * HALF);
    const int tt   = r / HALF;
    const int posA = r - tt * HALF;
    const int posB = posA + HALF;

    const float* gp = g_params + (long)(n * 3 + tt) * S_LEN * EDIM;

    float pA[16], pB[16];
    if (posA == 0) {
#pragma unroll
        for (int e = 0; e < 16; e++) {
            pA[e] = (tt == 0) ? softplus_f(ind_in_w[e])
                  : (tt == 1) ? ind_in_b[e]
                              : ind_out_w[e];
        }
    } else {
        const float4* src = (const float4*)(gp + (long)(posA - 1) * EDIM);
        const float4 a = src[0], b = src[1], c = src[2], d = src[3];
        pA[0]=a.x; pA[1]=a.y; pA[2]=a.z; pA[3]=a.w;
        pA[4]=b.x; pA[5]=b.y; pA[6]=b.z; pA[7]=b.w;
        pA[8]=c.x; pA[9]=c.y; pA[10]=c.z; pA[11]=c.w;
        pA[12]=d.x; pA[13]=d.y; pA[14]=d.z; pA[15]=d.w;
    }
    {
        const float4* src = (const float4*)(gp + (long)(posB - 1) * EDIM);
        const float4 a = src[0], b = src[1], c = src[2], d = src[3];
        pB[0]=a.x; pB[1]=a.y; pB[2]=a.z; pB[3]=a.w;
        pB[4]=b.x; pB[5]=b.y; pB[6]=b.z; pB[7]=b.w;
        pB[8]=c.x; pB[9]=c.y; pB[10]=c.z; pB[11]=c.w;
        pB[12]=d.x; pB[13]=d.y; pB[14]=d.z; pB[15]=d.w;
    }

    float accA[16], accB[16];
#pragma unroll
    for (int e = 0; e < 16; e++) { accA[e] = b2[e]; accB[e] = b2[e]; }

#pragma unroll
    for (int o = 0; o < 32; o++) {
        const float4* w1p = (const float4*)&w1[o * 16];
        const float4 W0 = w1p[0], W1 = w1p[1], W2 = w1p[2], W3 = w1p[3];
        // two independent dot chains, 2 accumulators each
        float hA0 = fmaf(pA[0], W0.x, 0.f),  hA1 = fmaf(pA[1], W0.y, 0.f);
        float hB0 = fmaf(pB[0], W0.x, 0.f),  hB1 = fmaf(pB[1], W0.y, 0.f);
        hA0 = fmaf(pA[2], W0.z, hA0); hA1 = fmaf(pA[3], W0.w, hA1);
        hB0 = fmaf(pB[2], W0.z, hB0); hB1 = fmaf(pB[3], W0.w, hB1);
        hA0 = fmaf(pA[4], W1.x, hA0); hA1 = fmaf(pA[5], W1.y, hA1);
        hB0 = fmaf(pB[4], W1.x, hB0); hB1 = fmaf(pB[5], W1.y, hB1);
        hA0 = fmaf(pA[6], W1.z, hA0); hA1 = fmaf(pA[7], W1.w, hA1);
        hB0 = fmaf(pB[6], W1.z, hB0); hB1 = fmaf(pB[7], W1.w, hB1);
        hA0 = fmaf(pA[8], W2.x, hA0); hA1 = fmaf(pA[9], W2.y, hA1);
        hB0 = fmaf(pB[8], W2.x, hB0); hB1 = fmaf(pB[9], W2.y, hB1);
        hA0 = fmaf(pA[10], W2.z, hA0); hA1 = fmaf(pA[11], W2.w, hA1);
        hB0 = fmaf(pB[10], W2.z, hB0); hB1 = fmaf(pB[11], W2.w, hB1);
        hA0 = fmaf(pA[12], W3.x, hA0); hA1 = fmaf(pA[13], W3.y, hA1);
        hB0 = fmaf(pB[12], W3.x, hB0); hB1 = fmaf(pB[13], W3.y, hB1);
        hA0 = fmaf(pA[14], W3.z, hA0); hA1 = fmaf(pA[15], W3.w, hA1);
        hB0 = fmaf(pB[14], W3.z, hB0); hB1 = fmaf(pB[15], W3.w, hB1);

        const float hA = fmaxf(hA0 + hA1 + b1[o], 0.0f);
        const float hB = fmaxf(hB0 + hB1 + b1[o], 0.0f);

        const float4* w2p = (const float4*)&w2t[o][0];
        const float4 V0 = w2p[0], V1 = w2p[1], V2 = w2p[2], V3 = w2p[3];
        accA[0] = fmaf(hA, V0.x, accA[0]);  accB[0] = fmaf(hB, V0.x, accB[0]);
        accA[1] = fmaf(hA, V0.y, accA[1]);  accB[1] = fmaf(hB, V0.y, accB[1]);
        accA[2] = fmaf(hA, V0.z, accA[2]);  accB[2] = fmaf(hB, V0.z, accB[2]);
        accA[3] = fmaf(hA, V0.w, accA[3]);  accB[3] = fmaf(hB, V0.w, accB[3]);
        accA[4] = fmaf(hA, V1.x, accA[4]);  accB[4] = fmaf(hB, V1.x, accB[4]);
        accA[5] = fmaf(hA, V1.y, accA[5]);  accB[5] = fmaf(hB, V1.y, accB[5]);
        accA[6] = fmaf(hA, V1.z, accA[6]);  accB[6] = fmaf(hB, V1.z, accB[6]);
        accA[7] = fmaf(hA, V1.w, accA[7]);  accB[7] = fmaf(hB, V1.w, accB[7]);
        accA[8] = fmaf(hA, V2.x, accA[8]);  accB[8] = fmaf(hB, V2.x, accB[8]);
        accA[9] = fmaf(hA, V2.y, accA[9]);  accB[9] = fmaf(hB, V2.y, accB[9]);
        accA[10] = fmaf(hA, V2.z, accA[10]); accB[10] = fmaf(hB, V2.z, accB[10]);
        accA[11] = fmaf(hA, V2.w, accA[11]); accB[11] = fmaf(hB, V2.w, accB[11]);
        accA[12] = fmaf(hA, V3.x, accA[12]); accB[12] = fmaf(hB, V3.x, accB[12]);
        accA[13] = fmaf(hA, V3.y, accA[13]); accB[13] = fmaf(hB, V3.y, accB[13]);
        accA[14] = fmaf(hA, V3.z, accA[14]); accB[14] = fmaf(hB, V3.z, accB[14]);
        accA[15] = fmaf(hA, V3.w, accA[15]); accB[15] = fmaf(hB, V3.w, accB[15]);
    }

    if (tt == 0) {   // in_proj_weight gets a final softplus
#pragma unroll
        for (int e = 0; e < 16; e++) {
            accA[e] = softplus_f(accA[e]);
            accB[e] = softplus_f(accB[e]);
        }
    }

    float* dbase = out + ((long)tt * NBATCH + n) * S_LEN * EDIM;
    float4* dA = (float4*)(dbase + (long)posA * EDIM);
    dA[0] = make_float4(accA[0],  accA[1],  accA[2],  accA[3]);
    dA[1] = make_float4(accA[4],  accA[5],  accA[6],  accA[7]);
    dA[2] = make_float4(accA[8],  accA[9],  accA[10], accA[11]);
    dA[3] = make_float4(accA[12], accA[13], accA[14], accA[15]);
    float4* dB = (float4*)(dbase + (long)posB * EDIM);
    dB[0] = make_float4(accB[0],  accB[1],  accB[2],  accB[3]);
    dB[1] = make_float4(accB[4],  accB[5],  accB[6],  accB[7]);
    dB[2] = make_float4(accB[8],  accB[9],  accB[10], accB[11]);
    dB[3] = make_float4(accB[12], accB[13], accB[14], accB[15]);
}

// ---------------------------------------------------------------------------
extern "C" void kernel_launch(void* const* d_in, const int* in_sizes, int n_in,
                              void* d_out, int out_size)
{
    const float* x         = (const float*)d_in[0];
    const float* ew        = (const float*)d_in[1];
    const float* eb        = (const float*)d_in[2];
    const float* ind_in_w  = (const float*)d_in[3];
    const float* ind_in_b  = (const float*)d_in[4];
    const float* ind_out_w = (const float*)d_in[5];
    const float* ind_out_b = (const float*)d_in[6];
    const float* ind_res_w = (const float*)d_in[7];
    const float* fc1_w     = (const float*)d_in[8];
    const float* fc1_b     = (const float*)d_in[9];
    const float* fc2_w     = (const float*)d_in[10];
    const float* fc2_b     = (const float*)d_in[11];
    float* out = (float*)d_out;

    scan_a<<<NCHAIN * SPLIT, 256>>>(x, ew, eb);
    scan_c<<<NCHAIN * SPLIT, 256>>>(x, ew, eb, ind_out_b, ind_res_w, out);
    mlp_kernel<<<(NBATCH * 3 * (S_LEN / 2)) / 128, 128>>>(
        ind_in_w, ind_in_b, ind_out_w, fc1_w, fc1_b, fc2_w, fc2_b, out);
}

// round 6
// speedup vs baseline: 1.1750x; 1.0312x over previous
#include <cuda_runtime.h>

#define S_LEN   3072
#define EDIM    16
#define NHEAD   5
#define NBATCH  32
#define NCHAIN  (NBATCH * NHEAD)   // 160
#define SPLIT   4
#define SEG_LEN (S_LEN / SPLIT)    // 768
#define CHUNKS  32
#define CLEN    (SEG_LEN / CHUNKS) // 24

// q->k and q->v offsets in float2 units (folded into LDG immediates)
#define KOFF2 (NHEAD * S_LEN * 8)
#define VOFF2 (2 * NHEAD * S_LEN * 8)

// scratch for params of heads 0..2 (inner): [N][3][S_LEN][E]
__device__ float g_params[(long)NBATCH * 3 * S_LEN * EDIM];
// chunk-prefix scratch: per (chain,seg) block: 32 chunks x 256 S-entries / 16 z
__device__ float g_prefS[(long)NCHAIN * SPLIT * CHUNKS * 256];
__device__ float g_prefZ[(long)NCHAIN * SPLIT * CHUNKS * 16];
__device__ float g_totS [(long)NCHAIN * SPLIT * 256];
__device__ float g_totZ [(long)NCHAIN * SPLIT * 16];

__device__ __forceinline__ float softplus_f(float x) {
    // all args here are small (|x| < ~4): unclamped fast form is exact enough
    return __logf(1.0f + __expf(x));
}

// ---------------------------------------------------------------------------
// K1: per-chunk sums of k (z) and k v^T (S), exclusive prefix within segment,
// prefixes + segment totals -> global scratch.
// grid = 640 (chain,seg), block = 256 = 32 groups x 8 lanes (2 cols/lane).
// ---------------------------------------------------------------------------
__global__ __launch_bounds__(256, 4) void scan_a(
    const float* __restrict__ x,
    const float* __restrict__ ew,
    const float* __restrict__ eb)
{
    __shared__ __align__(16) float kst[2][CHUNKS][16];
    __shared__ float sS[CHUNKS][16][16];
    __shared__ float sZ[CHUNKS][16];

    const int b     = blockIdx.x;
    const int chain = b >> 2, seg = b & 3;
    const int n     = chain / NHEAD, head = chain % NHEAD;
    const int tid   = threadIdx.x;
    const int g     = tid >> 3, hl = tid & 7;

    const float* xw = x + (long)n * S_LEN;
    const int pos0  = seg * SEG_LEN + g * CLEN;

    // base pointers at q-head; k/v reached via constant immediate offsets
    const long qbase = (long)head * S_LEN * 8 + (long)pos0 * 8 + hl;
    const float2* wq = (const float2*)ew + qbase;
    const float2* bq = (const float2*)eb + qbase;

    float S0[16], S1[16];
#pragma unroll
    for (int i = 0; i < 16; i++) { S0[i] = 0.f; S1[i] = 0.f; }
    float z0 = 0.f, z1 = 0.f;

    for (int s = 0; s < CLEN; s++) {
        const float xv = __ldg(xw + pos0 + s);
        const float2 a  = __ldg(wq + KOFF2 + s * 8);
        const float2 bb = __ldg(bq + KOFF2 + s * 8);
        const float kx = softplus_f(fmaf(a.x, xv, bb.x));
        const float ky = softplus_f(fmaf(a.y, xv, bb.y));
        const float2 c  = __ldg(wq + VOFF2 + s * 8);
        const float2 d  = __ldg(bq + VOFF2 + s * 8);
        const float vx = fmaf(c.x, xv, d.x);
        const float vy = fmaf(c.y, xv, d.y);
        z0 += kx; z1 += ky;

        const int buf = s & 1;
        *(float2*)&kst[buf][g][2 * hl] = make_float2(kx, ky);
        __syncwarp();
        const float4* kv = (const float4*)kst[buf][g];
        const float4 K0 = kv[0], K1 = kv[1], K2 = kv[2], K3 = kv[3];
        const float kk[16] = {K0.x,K0.y,K0.z,K0.w, K1.x,K1.y,K1.z,K1.w,
                              K2.x,K2.y,K2.z,K2.w, K3.x,K3.y,K3.z,K3.w};
#pragma unroll
        for (int i = 0; i < 16; i++) {
            S0[i] = fmaf(kk[i], vx, S0[i]);
            S1[i] = fmaf(kk[i], vy, S1[i]);
        }
    }

#pragma unroll
    for (int i = 0; i < 16; i++)
        *(float2*)&sS[g][i][2 * hl] = make_float2(S0[i], S1[i]);
    *(float2*)&sZ[g][2 * hl] = make_float2(z0, z1);
    __syncthreads();

    // serial exclusive scan over chunks; 256 S entries (+16 z on tid<16)
    {
        const int i = tid >> 4, c = tid & 15;
        float run = 0.f;
        const long base = ((long)b * CHUNKS) * 256 + tid;
        for (int gg = 0; gg < CHUNKS; gg++) {
            g_prefS[base + gg * 256] = run;
            run += sS[gg][i][c];
        }
        g_totS[(long)b * 256 + tid] = run;
        if (tid < 16) {
            float rz = 0.f;
            const long bz = ((long)b * CHUNKS) * 16 + tid;
            for (int gg = 0; gg < CHUNKS; gg++) {
                g_prefZ[bz + gg * 16] = rz;
                rz += sZ[gg][tid];
            }
            g_totZ[b * 16 + tid] = rz;
        }
    }
}

// ---------------------------------------------------------------------------
// K2: exclusive prefix of segment totals across SPLIT segments of each chain
// (in place). grid = 160, block = 272.
// ---------------------------------------------------------------------------
__global__ void scan_b()
{
    const int chain = blockIdx.x;
    const int t = threadIdx.x;
    if (t < 256) {
        float run = 0.f;
        for (int s = 0; s < SPLIT; s++) {
            const long idx = ((long)chain * SPLIT + s) * 256 + t;
            const float v = g_totS[idx]; g_totS[idx] = run; run += v;
        }
    } else if (t < 272) {
        const int i = t - 256;
        float run = 0.f;
        for (int s = 0; s < SPLIT; s++) {
            const long idx = ((long)chain * SPLIT + s) * 16 + i;
            const float v = g_totZ[idx]; g_totZ[idx] = run; run += v;
        }
    }
}

// ---------------------------------------------------------------------------
// K3: rescan each chunk from its prefix state with q; emit params
// (heads 0-2 -> scratch) or e-summed shifted outputs (heads 3-4 -> d_out).
// ---------------------------------------------------------------------------
__global__ __launch_bounds__(256, 4) void scan_c(
    const float* __restrict__ x,
    const float* __restrict__ ew,
    const float* __restrict__ eb,
    const float* __restrict__ ind_out_b,
    const float* __restrict__ ind_res_w,
    float* __restrict__ out)
{
    __shared__ __align__(16) float st[2][CHUNKS][32];  // [buf][grp][k:0..15|q:16..31]

    const int b     = blockIdx.x;
    const int chain = b >> 2, seg = b & 3;
    const int n     = chain / NHEAD, head = chain % NHEAD;
    const int tid   = threadIdx.x;
    const int g     = tid >> 3, hl = tid & 7;

    const float* xw = x + (long)n * S_LEN;
    const int pos0  = seg * SEG_LEN + g * CLEN;

    const long qbase = (long)head * S_LEN * 8 + (long)pos0 * 8 + hl;
    const float2* wq = (const float2*)ew + qbase;
    const float2* bq = (const float2*)eb + qbase;

    // prefix state: chunk prefix + exclusive segment total (tot is exclusive
    // after scan_b, so we always add it)
    float S0[16], S1[16], z0, z1;
    {
        const long pb = ((long)b * CHUNKS + g) * 256;
        const long tb = (long)b * 256;
#pragma unroll
        for (int i = 0; i < 16; i++) {
            const float2 p = *(const float2*)&g_prefS[pb + i * 16 + 2 * hl];
            const float2 t = *(const float2*)&g_totS[tb + i * 16 + 2 * hl];
            S0[i] = p.x + t.x; S1[i] = p.y + t.y;
        }
        const float2 pz = *(const float2*)&g_prefZ[((long)b * CHUNKS + g) * 16 + 2 * hl];
        const float2 tz = *(const float2*)&g_totZ[(long)b * 16 + 2 * hl];
        z0 = pz.x + tz.x; z1 = pz.y + tz.y;
    }

    const bool isInner = (head < 3);
    float* pdst = nullptr;
    float* odst = nullptr;
    if (isInner) {
        pdst = g_params + ((long)(n * 3 + head) * S_LEN) * EDIM;
    } else {
        const long base = (long)3 * NBATCH * S_LEN * EDIM
                        + (long)(head - 3) * NBATCH * S_LEN;
        odst = out + base + (long)n * S_LEN;
        if (tid == 0 && seg == 0)
            odst[0] = (head == 3) ? ind_out_b[0] : ind_res_w[0];
    }

    for (int s = 0; s < CLEN; s++) {
        const int pos = pos0 + s;
        const float xv = __ldg(xw + pos);
        float2 a, c;
        a = __ldg(wq + s * 8);         c = __ldg(bq + s * 8);
        const float qx = softplus_f(fmaf(a.x, xv, c.x));
        const float qy = softplus_f(fmaf(a.y, xv, c.y));
        a = __ldg(wq + KOFF2 + s * 8); c = __ldg(bq + KOFF2 + s * 8);
        const float kx = softplus_f(fmaf(a.x, xv, c.x));
        const float ky = softplus_f(fmaf(a.y, xv, c.y));
        a = __ldg(wq + VOFF2 + s * 8); c = __ldg(bq + VOFF2 + s * 8);
        const float vx = fmaf(a.x, xv, c.x);
        const float vy = fmaf(a.y, xv, c.y);

        z0 += kx; z1 += ky;

        const int buf = s & 1;
        *(float2*)&st[buf][g][2 * hl]      = make_float2(kx, ky);
        *(float2*)&st[buf][g][16 + 2 * hl] = make_float2(qx, qy);
        __syncwarp();

        float dp = fmaf(qx, z0, qy * z1);
        dp += __shfl_xor_sync(0xffffffffu, dp, 1, 8);
        dp += __shfl_xor_sync(0xffffffffu, dp, 2, 8);
        dp += __shfl_xor_sync(0xffffffffu, dp, 4, 8);

        const float4* kv = (const float4*)&st[buf][g][0];
        const float4* qv = (const float4*)&st[buf][g][16];
        float num0 = 0.f, num1 = 0.f;
#pragma unroll
        for (int q4 = 0; q4 < 4; q4++) {
            const float4 K = kv[q4];
            const float4 Q = qv[q4];
            S0[4*q4+0] = fmaf(K.x, vx, S0[4*q4+0]); num0 = fmaf(Q.x, S0[4*q4+0], num0);
            S0[4*q4+1] = fmaf(K.y, vx, S0[4*q4+1]); num0 = fmaf(Q.y, S0[4*q4+1], num0);
            S0[4*q4+2] = fmaf(K.z, vx, S0[4*q4+2]); num0 = fmaf(Q.z, S0[4*q4+2], num0);
            S0[4*q4+3] = fmaf(K.w, vx, S0[4*q4+3]); num0 = fmaf(Q.w, S0[4*q4+3], num0);
            S1[4*q4+0] = fmaf(K.x, vy, S1[4*q4+0]); num1 = fmaf(Q.x, S1[4*q4+0], num1);
            S1[4*q4+1] = fmaf(K.y, vy, S1[4*q4+1]); num1 = fmaf(Q.y, S1[4*q4+1], num1);
            S1[4*q4+2] = fmaf(K.z, vy, S1[4*q4+2]); num1 = fmaf(Q.z, S1[4*q4+2], num1);
            S1[4*q4+3] = fmaf(K.w, vy, S1[4*q4+3]); num1 = fmaf(Q.w, S1[4*q4+3], num1);
        }
        const float r = __fdividef(1.0f, dp);
        const float p0 = num0 * r, p1 = num1 * r;

        if (isInner) {
            *(float2*)&pdst[(long)pos * EDIM + 2 * hl] = make_float2(p0, p1);
        } else {
            float tot = p0 + p1;
            tot += __shfl_xor_sync(0xffffffffu, tot, 1, 8);
            tot += __shfl_xor_sync(0xffffffffu, tot, 2, 8);
            tot += __shfl_xor_sync(0xffffffffu, tot, 4, 8);
            if (hl == 0 && pos + 1 < S_LEN)
                odst[pos + 1] = tot;
        }
    }
}

// ---------------------------------------------------------------------------
// K4: per-position MLP for heads 0..2 on shifted params.
// 2 positions per thread (pos, pos+1536) sharing every weight load.
// ---------------------------------------------------------------------------
__global__ __launch_bounds__(128) void mlp_kernel(
    const float* __restrict__ ind_in_w,
    const float* __restrict__ ind_in_b,
    const float* __restrict__ ind_out_w,
    const float* __restrict__ fc1_w,
    const float* __restrict__ fc1_b,
    const float* __restrict__ fc2_w,
    const float* __restrict__ fc2_b,
    float* __restrict__ out)
{
    __shared__ __align__(16) float w1[32 * 16];
    __shared__ __align__(16) float w2t[32][16];   // transposed: [o][e]
    __shared__ float b1[32];
    __shared__ float b2[16];

    const int tid = threadIdx.x;
    for (int i = tid; i < 512; i += 128) w1[i] = fc1_w[i];
    for (int i = tid; i < 512; i += 128) {
        const int p = i >> 5, o = i & 31;   // fc2_w is [E][2E] row-major
        w2t[o][p] = fc2_w[i];
    }
    if (tid < 32) b1[tid] = fc1_b[tid];
    if (tid < 16) b2[tid] = fc2_b[tid];
    __syncthreads();

    const int HALF = S_LEN / 2;                  // 1536
    const int t    = blockIdx.x * 128 + tid;     // 0 .. 147455
    const int n    = t / (3 * HALF);
    const int r    = t - n * (3 * HALF);
    const int tt   = r / HALF;
    const int posA = r - tt * HALF;
    const int posB = posA + HALF;

    const float* gp = g_params + (long)(n * 3 + tt) * S_LEN * EDIM;

    float pA[16], pB[16];
    if (posA == 0) {
#pragma unroll
        for (int e = 0; e < 16; e++) {
            pA[e] = (tt == 0) ? softplus_f(ind_in_w[e])
                  : (tt == 1) ? ind_in_b[e]
                              : ind_out_w[e];
        }
    } else {
        const float4* src = (const float4*)(gp + (long)(posA - 1) * EDIM);
        const float4 a = src[0], b = src[1], c = src[2], d = src[3];
        pA[0]=a.x; pA[1]=a.y; pA[2]=a.z; pA[3]=a.w;
        pA[4]=b.x; pA[5]=b.y; pA[6]=b.z; pA[7]=b.w;
        pA[8]=c.x; pA[9]=c.y; pA[10]=c.z; pA[11]=c.w;
        pA[12]=d.x; pA[13]=d.y; pA[14]=d.z; pA[15]=d.w;
    }
    {
        const float4* src = (const float4*)(gp + (long)(posB - 1) * EDIM);
        const float4 a = src[0], b = src[1], c = src[2], d = src[3];
        pB[0]=a.x; pB[1]=a.y; pB[2]=a.z; pB[3]=a.w;
        pB[4]=b.x; pB[5]=b.y; pB[6]=b.z; pB[7]=b.w;
        pB[8]=c.x; pB[9]=c.y; pB[10]=c.z; pB[11]=c.w;
        pB[12]=d.x; pB[13]=d.y; pB[14]=d.z; pB[15]=d.w;
    }

    float accA[16], accB[16];
#pragma unroll
    for (int e = 0; e < 16; e++) { accA[e] = b2[e]; accB[e] = b2[e]; }

#pragma unroll
    for (int o = 0; o < 32; o++) {
        const float4* w1p = (const float4*)&w1[o * 16];
        const float4 W0 = w1p[0], W1 = w1p[1], W2 = w1p[2], W3 = w1p[3];
        float hA0 = fmaf(pA[0], W0.x, 0.f),  hA1 = fmaf(pA[1], W0.y, 0.f);
        float hB0 = fmaf(pB[0], W0.x, 0.f),  hB1 = fmaf(pB[1], W0.y, 0.f);
        hA0 = fmaf(pA[2], W0.z, hA0); hA1 = fmaf(pA[3], W0.w, hA1);
        hB0 = fmaf(pB[2], W0.z, hB0); hB1 = fmaf(pB[3], W0.w, hB1);
        hA0 = fmaf(pA[4], W1.x, hA0); hA1 = fmaf(pA[5], W1.y, hA1);
        hB0 = fmaf(pB[4], W1.x, hB0); hB1 = fmaf(pB[5], W1.y, hB1);
        hA0 = fmaf(pA[6], W1.z, hA0); hA1 = fmaf(pA[7], W1.w, hA1);
        hB0 = fmaf(pB[6], W1.z, hB0); hB1 = fmaf(pB[7], W1.w, hB1);
        hA0 = fmaf(pA[8], W2.x, hA0); hA1 = fmaf(pA[9], W2.y, hA1);
        hB0 = fmaf(pB[8], W2.x, hB0); hB1 = fmaf(pB[9], W2.y, hB1);
        hA0 = fmaf(pA[10], W2.z, hA0); hA1 = fmaf(pA[11], W2.w, hA1);
        hB0 = fmaf(pB[10], W2.z, hB0); hB1 = fmaf(pB[11], W2.w, hB1);
        hA0 = fmaf(pA[12], W3.x, hA0); hA1 = fmaf(pA[13], W3.y, hA1);
        hB0 = fmaf(pB[12], W3.x, hB0); hB1 = fmaf(pB[13], W3.y, hB1);
        hA0 = fmaf(pA[14], W3.z, hA0); hA1 = fmaf(pA[15], W3.w, hA1);
        hB0 = fmaf(pB[14], W3.z, hB0); hB1 = fmaf(pB[15], W3.w, hB1);

        const float hA = fmaxf(hA0 + hA1 + b1[o], 0.0f);
        const float hB = fmaxf(hB0 + hB1 + b1[o], 0.0f);

        const float4* w2p = (const float4*)&w2t[o][0];
        const float4 V0 = w2p[0], V1 = w2p[1], V2 = w2p[2], V3 = w2p[3];
        accA[0] = fmaf(hA, V0.x, accA[0]);  accB[0] = fmaf(hB, V0.x, accB[0]);
        accA[1] = fmaf(hA, V0.y, accA[1]);  accB[1] = fmaf(hB, V0.y, accB[1]);
        accA[2] = fmaf(hA, V0.z, accA[2]);  accB[2] = fmaf(hB, V0.z, accB[2]);
        accA[3] = fmaf(hA, V0.w, accA[3]);  accB[3] = fmaf(hB, V0.w, accB[3]);
        accA[4] = fmaf(hA, V1.x, accA[4]);  accB[4] = fmaf(hB, V1.x, accB[4]);
        accA[5] = fmaf(hA, V1.y, accA[5]);  accB[5] = fmaf(hB, V1.y, accB[5]);
        accA[6] = fmaf(hA, V1.z, accA[6]);  accB[6] = fmaf(hB, V1.z, accB[6]);
        accA[7] = fmaf(hA, V1.w, accA[7]);  accB[7] = fmaf(hB, V1.w, accB[7]);
        accA[8] = fmaf(hA, V2.x, accA[8]);  accB[8] = fmaf(hB, V2.x, accB[8]);
        accA[9] = fmaf(hA, V2.y, accA[9]);  accB[9] = fmaf(hB, V2.y, accB[9]);
        accA[10] = fmaf(hA, V2.z, accA[10]); accB[10] = fmaf(hB, V2.z, accB[10]);
        accA[11] = fmaf(hA, V2.w, accA[11]); accB[11] = fmaf(hB, V2.w, accB[11]);
        accA[12] = fmaf(hA, V3.x, accA[12]); accB[12] = fmaf(hB, V3.x, accB[12]);
        accA[13] = fmaf(hA, V3.y, accA[13]); accB[13] = fmaf(hB, V3.y, accB[13]);
        accA[14] = fmaf(hA, V3.z, accA[14]); accB[14] = fmaf(hB, V3.z, accB[14]);
        accA[15] = fmaf(hA, V3.w, accA[15]); accB[15] = fmaf(hB, V3.w, accB[15]);
    }

    if (tt == 0) {   // in_proj_weight gets a final softplus
#pragma unroll
        for (int e = 0; e < 16; e++) {
            accA[e] = softplus_f(accA[e]);
            accB[e] = softplus_f(accB[e]);
        }
    }

    float* dbase = out + ((long)tt * NBATCH + n) * S_LEN * EDIM;
    float4* dA = (float4*)(dbase + (long)posA * EDIM);
    dA[0] = make_float4(accA[0],  accA[1],  accA[2],  accA[3]);
    dA[1] = make_float4(accA[4],  accA[5],  accA[6],  accA[7]);
    dA[2] = make_float4(accA[8],  accA[9],  accA[10], accA[11]);
    dA[3] = make_float4(accA[12], accA[13], accA[14], accA[15]);
    float4* dB = (float4*)(dbase + (long)posB * EDIM);
    dB[0] = make_float4(accB[0],  accB[1],  accB[2],  accB[3]);
    dB[1] = make_float4(accB[4],  accB[5],  accB[6],  accB[7]);
    dB[2] = make_float4(accB[8],  accB[9],  accB[10], accB[11]);
    dB[3] = make_float4(accB[12], accB[13], accB[14], accB[15]);
}

// ---------------------------------------------------------------------------
extern "C" void kernel_launch(void* const* d_in, const int* in_sizes, int n_in,
                              void* d_out, int out_size)
{
    const float* x         = (const float*)d_in[0];
    const float* ew        = (const float*)d_in[1];
    const float* eb        = (const float*)d_in[2];
    const float* ind_in_w  = (const float*)d_in[3];
    const float* ind_in_b  = (const float*)d_in[4];
    const float* ind_out_w = (const float*)d_in[5];
    const float* ind_out_b = (const float*)d_in[6];
    const float* ind_res_w = (const float*)d_in[7];
    const float* fc1_w     = (const float*)d_in[8];
    const float* fc1_b     = (const float*)d_in[9];
    const float* fc2_w     = (const float*)d_in[10];
    const float* fc2_b     = (const float*)d_in[11];
    float* out = (float*)d_out;

    scan_a<<<NCHAIN * SPLIT, 256>>>(x, ew, eb);
    scan_b<<<NCHAIN, 272>>>();
    scan_c<<<NCHAIN * SPLIT, 256>>>(x, ew, eb, ind_out_b, ind_res_w, out);
    mlp_kernel<<<(NBATCH * 3 * (S_LEN / 2)) / 128, 128>>>(
        ind_in_w, ind_in_b, ind_out_w, fc1_w, fc1_b, fc2_w, fc2_b, out);
}

// round 7
// speedup vs baseline: 1.3020x; 1.1081x over previous
#include <cuda_runtime.h>

#define S_LEN   3072
#define EDIM    16
#define NHEAD   5
#define NBATCH  32
#define NCHAIN  (NBATCH * NHEAD)   // 160
#define SPLIT   8
#define SEG_LEN (S_LEN / SPLIT)    // 384
#define CHUNKS  16
#define CLEN    (SEG_LEN / CHUNKS) // 24
#define NPAIR   (NBATCH / 2)       // 16

// q->k and q->v offsets in float2 units (folded into LDG immediates)
#define KOFF2 (NHEAD * S_LEN * 8)
#define VOFF2 (2 * NHEAD * S_LEN * 8)

// scratch for params of heads 0..2 (inner): [N][3][S_LEN][E]
__device__ float g_params[(long)NBATCH * 3 * S_LEN * EDIM];
// chunk sums -> exclusive prefixes (in-place): [chain*SPLIT+seg][chunk][i][c]
__device__ float g_prefS[(long)NCHAIN * SPLIT * CHUNKS * 256];
__device__ float g_prefZ[(long)NCHAIN * SPLIT * CHUNKS * 16];
__device__ float g_totS [(long)NCHAIN * SPLIT * 256];
__device__ float g_totZ [(long)NCHAIN * SPLIT * 16];

__device__ __forceinline__ float softplus_f(float x) {
    // all args here are small (|x| < ~5): unclamped fast form is exact enough
    return __logf(1.0f + __expf(x));
}

// ---------------------------------------------------------------------------
// K1: batch-paired chunk sums + in-segment exclusive prefix.
// grid = NHEAD*SPLIT*NPAIR = 640, block = 256 = 16 chunks x (2 batches x 8).
// Lanes 0-7 of each 16-lane supergroup serve batch pair*2, lanes 8-15 serve
// pair*2+1; weight LDG addresses coincide across the two halves -> L1 sector
// dedup halves weight wavefronts.
// ---------------------------------------------------------------------------
__global__ __launch_bounds__(256, 4) void scan_a(
    const float* __restrict__ x,
    const float* __restrict__ ew,
    const float* __restrict__ eb)
{
    __shared__ __align__(16) float kst[2][CHUNKS][2][16];
    __shared__ float sZ[CHUNKS][2][16];

    const int b    = blockIdx.x;
    const int pair = b / (NHEAD * SPLIT);
    const int rem  = b % (NHEAD * SPLIT);
    const int seg  = rem / NHEAD;
    const int head = rem % NHEAD;
    const int tid  = threadIdx.x;
    const int g    = tid >> 4;          // chunk 0..15
    const int sub  = (tid >> 3) & 1;    // batch half
    const int hl   = tid & 7;

    const int n     = pair * 2 + sub;
    const int chain = n * NHEAD + head;
    const float* xw = x + (long)n * S_LEN;
    const int pos0  = seg * SEG_LEN + g * CLEN;

    const long qbase = (long)head * S_LEN * 8 + (long)pos0 * 8 + hl;
    const float2* wq = (const float2*)ew + qbase;
    const float2* bq = (const float2*)eb + qbase;

    float S0[16], S1[16];
#pragma unroll
    for (int i = 0; i < 16; i++) { S0[i] = 0.f; S1[i] = 0.f; }
    float z0 = 0.f, z1 = 0.f;

    for (int s = 0; s < CLEN; s++) {
        const float xv = __ldg(xw + pos0 + s);
        const float2 a  = __ldg(wq + KOFF2 + s * 8);
        const float2 bb = __ldg(bq + KOFF2 + s * 8);
        const float kx = softplus_f(fmaf(a.x, xv, bb.x));
        const float ky = softplus_f(fmaf(a.y, xv, bb.y));
        const float2 c  = __ldg(wq + VOFF2 + s * 8);
        const float2 d  = __ldg(bq + VOFF2 + s * 8);
        const float vx = fmaf(c.x, xv, d.x);
        const float vy = fmaf(c.y, xv, d.y);
        z0 += kx; z1 += ky;

        const int buf = s & 1;
        *(float2*)&kst[buf][g][sub][2 * hl] = make_float2(kx, ky);
        __syncwarp();
        const float4* kv = (const float4*)kst[buf][g][sub];
        const float4 K0 = kv[0], K1 = kv[1], K2 = kv[2], K3 = kv[3];
        const float kk[16] = {K0.x,K0.y,K0.z,K0.w, K1.x,K1.y,K1.z,K1.w,
                              K2.x,K2.y,K2.z,K2.w, K3.x,K3.y,K3.z,K3.w};
#pragma unroll
        for (int i = 0; i < 16; i++) {
            S0[i] = fmaf(kk[i], vx, S0[i]);
            S1[i] = fmaf(kk[i], vy, S1[i]);
        }
    }

    // chunk sums -> global ([b][chunk][i][c] layout), z -> smem
    {
        const long pb = ((long)(chain * SPLIT + seg) * CHUNKS + g) * 256;
#pragma unroll
        for (int i = 0; i < 16; i++)
            *(float2*)&g_prefS[pb + i * 16 + 2 * hl] = make_float2(S0[i], S1[i]);
    }
    *(float2*)&sZ[g][sub][2 * hl] = make_float2(z0, z1);
    __syncthreads();

    // in-place exclusive scan over chunks (L2-hot); both batch halves
    {
        const int i = tid >> 4, c = tid & 15;
#pragma unroll
        for (int sub2 = 0; sub2 < 2; sub2++) {
            const int chain2 = (pair * 2 + sub2) * NHEAD + head;
            const long base = ((long)(chain2 * SPLIT + seg) * CHUNKS) * 256
                            + i * 16 + c;
            float run = 0.f;
#pragma unroll
            for (int gg = 0; gg < CHUNKS; gg++) {
                const float t = g_prefS[base + gg * 256];
                g_prefS[base + gg * 256] = run;
                run += t;
            }
            g_totS[(long)(chain2 * SPLIT + seg) * 256 + i * 16 + c] = run;
        }
    }
    if (tid < 32) {
        const int sub2 = tid >> 4, i2 = tid & 15;
        const int chain2 = (pair * 2 + sub2) * NHEAD + head;
        const long bz = (long)(chain2 * SPLIT + seg) * CHUNKS * 16 + i2;
        float rz = 0.f;
#pragma unroll
        for (int gg = 0; gg < CHUNKS; gg++) {
            g_prefZ[bz + gg * 16] = rz;
            rz += sZ[gg][sub2][i2];
        }
        g_totZ[(long)(chain2 * SPLIT + seg) * 16 + i2] = rz;
    }
}

// ---------------------------------------------------------------------------
// K2: exclusive prefix of segment totals across SPLIT segments of each chain
// (in place). grid = 160, block = 272.
// ---------------------------------------------------------------------------
__global__ void scan_b()
{
    const int chain = blockIdx.x;
    const int t = threadIdx.x;
    if (t < 256) {
        float run = 0.f;
#pragma unroll
        for (int s = 0; s < SPLIT; s++) {
            const long idx = ((long)chain * SPLIT + s) * 256 + t;
            const float v = g_totS[idx]; g_totS[idx] = run; run += v;
        }
    } else if (t < 272) {
        const int i = t - 256;
        float run = 0.f;
#pragma unroll
        for (int s = 0; s < SPLIT; s++) {
            const long idx = ((long)chain * SPLIT + s) * 16 + i;
            const float v = g_totZ[idx]; g_totZ[idx] = run; run += v;
        }
    }
}

// ---------------------------------------------------------------------------
// K3: batch-paired rescan from prefix state with q; emit params (heads 0-2 ->
// scratch) or e-summed shifted outputs (heads 3-4 -> d_out).
// ---------------------------------------------------------------------------
__global__ __launch_bounds__(256, 4) void scan_c(
    const float* __restrict__ x,
    const float* __restrict__ ew,
    const float* __restrict__ eb,
    const float* __restrict__ ind_out_b,
    const float* __restrict__ ind_res_w,
    float* __restrict__ out)
{
    __shared__ __align__(16) float st[2][CHUNKS][2][32];  // [buf][chunk][sub][k|q]

    const int b    = blockIdx.x;
    const int pair = b / (NHEAD * SPLIT);
    const int rem  = b % (NHEAD * SPLIT);
    const int seg  = rem / NHEAD;
    const int head = rem % NHEAD;
    const int tid  = threadIdx.x;
    const int g    = tid >> 4;
    const int sub  = (tid >> 3) & 1;
    const int hl   = tid & 7;

    const int n     = pair * 2 + sub;
    const int chain = n * NHEAD + head;
    const float* xw = x + (long)n * S_LEN;
    const int pos0  = seg * SEG_LEN + g * CLEN;

    const long qbase = (long)head * S_LEN * 8 + (long)pos0 * 8 + hl;
    const float2* wq = (const float2*)ew + qbase;
    const float2* bq = (const float2*)eb + qbase;

    // prefix state = chunk prefix + exclusive segment total
    float S0[16], S1[16], z0, z1;
    {
        const long pb = ((long)(chain * SPLIT + seg) * CHUNKS + g) * 256;
        const long tb = (long)(chain * SPLIT + seg) * 256;
#pragma unroll
        for (int i = 0; i < 16; i++) {
            const float2 p = *(const float2*)&g_prefS[pb + i * 16 + 2 * hl];
            const float2 t = *(const float2*)&g_totS[tb + i * 16 + 2 * hl];
            S0[i] = p.x + t.x; S1[i] = p.y + t.y;
        }
        const float2 pz = *(const float2*)&g_prefZ[
            ((long)(chain * SPLIT + seg) * CHUNKS + g) * 16 + 2 * hl];
        const float2 tz = *(const float2*)&g_totZ[
            (long)(chain * SPLIT + seg) * 16 + 2 * hl];
        z0 = pz.x + tz.x; z1 = pz.y + tz.y;
    }

    const bool isInner = (head < 3);
    float* pdst = nullptr;
    float* odst = nullptr;
    if (isInner) {
        pdst = g_params + ((long)(n * 3 + head) * S_LEN) * EDIM;
    } else {
        const long base = (long)3 * NBATCH * S_LEN * EDIM
                        + (long)(head - 3) * NBATCH * S_LEN;
        odst = out + base + (long)n * S_LEN;
        if (g == 0 && hl == 0 && seg == 0)
            odst[0] = (head == 3) ? ind_out_b[0] : ind_res_w[0];
    }

    for (int s = 0; s < CLEN; s++) {
        const int pos = pos0 + s;
        const float xv = __ldg(xw + pos);
        float2 a, c;
        a = __ldg(wq + s * 8);         c = __ldg(bq + s * 8);
        const float qx = softplus_f(fmaf(a.x, xv, c.x));
        const float qy = softplus_f(fmaf(a.y, xv, c.y));
        a = __ldg(wq + KOFF2 + s * 8); c = __ldg(bq + KOFF2 + s * 8);
        const float kx = softplus_f(fmaf(a.x, xv, c.x));
        const float ky = softplus_f(fmaf(a.y, xv, c.y));
        a = __ldg(wq + VOFF2 + s * 8); c = __ldg(bq + VOFF2 + s * 8);
        const float vx = fmaf(a.x, xv, c.x);
        const float vy = fmaf(a.y, xv, c.y);

        z0 += kx; z1 += ky;

        const int buf = s & 1;
        *(float2*)&st[buf][g][sub][2 * hl]      = make_float2(kx, ky);
        *(float2*)&st[buf][g][sub][16 + 2 * hl] = make_float2(qx, qy);
        __syncwarp();

        float dp = fmaf(qx, z0, qy * z1);
        dp += __shfl_xor_sync(0xffffffffu, dp, 1, 8);
        dp += __shfl_xor_sync(0xffffffffu, dp, 2, 8);
        dp += __shfl_xor_sync(0xffffffffu, dp, 4, 8);

        const float4* kv = (const float4*)&st[buf][g][sub][0];
        const float4* qv = (const float4*)&st[buf][g][sub][16];
        float num0 = 0.f, num1 = 0.f;
#pragma unroll
        for (int q4 = 0; q4 < 4; q4++) {
            const float4 K = kv[q4];
            const float4 Q = qv[q4];
            S0[4*q4+0] = fmaf(K.x, vx, S0[4*q4+0]); num0 = fmaf(Q.x, S0[4*q4+0], num0);
            S0[4*q4+1] = fmaf(K.y, vx, S0[4*q4+1]); num0 = fmaf(Q.y, S0[4*q4+1], num0);
            S0[4*q4+2] = fmaf(K.z, vx, S0[4*q4+2]); num0 = fmaf(Q.z, S0[4*q4+2], num0);
            S0[4*q4+3] = fmaf(K.w, vx, S0[4*q4+3]); num0 = fmaf(Q.w, S0[4*q4+3], num0);
            S1[4*q4+0] = fmaf(K.x, vy, S1[4*q4+0]); num1 = fmaf(Q.x, S1[4*q4+0], num1);
            S1[4*q4+1] = fmaf(K.y, vy, S1[4*q4+1]); num1 = fmaf(Q.y, S1[4*q4+1], num1);
            S1[4*q4+2] = fmaf(K.z, vy, S1[4*q4+2]); num1 = fmaf(Q.z, S1[4*q4+2], num1);
            S1[4*q4+3] = fmaf(K.w, vy, S1[4*q4+3]); num1 = fmaf(Q.w, S1[4*q4+3], num1);
        }
        const float r = __fdividef(1.0f, dp);
        const float p0 = num0 * r, p1 = num1 * r;

        if (isInner) {
            *(float2*)&pdst[(long)pos * EDIM + 2 * hl] = make_float2(p0, p1);
        } else {
            float tot = p0 + p1;
            tot += __shfl_xor_sync(0xffffffffu, tot, 1, 8);
            tot += __shfl_xor_sync(0xffffffffu, tot, 2, 8);
            tot += __shfl_xor_sync(0xffffffffu, tot, 4, 8);
            if (hl == 0 && pos + 1 < S_LEN)
                odst[pos + 1] = tot;
        }
    }
}

// ---------------------------------------------------------------------------
// K4: per-position MLP for heads 0..2 on shifted params.
// 2 positions per thread (pos, pos+1536) sharing every weight load.
// ---------------------------------------------------------------------------
__global__ __launch_bounds__(128) void mlp_kernel(
    const float* __restrict__ ind_in_w,
    const float* __restrict__ ind_in_b,
    const float* __restrict__ ind_out_w,
    const float* __restrict__ fc1_w,
    const float* __restrict__ fc1_b,
    const float* __restrict__ fc2_w,
    const float* __restrict__ fc2_b,
    float* __restrict__ out)
{
    __shared__ __align__(16) float w1[32 * 16];
    __shared__ __align__(16) float w2t[32][16];   // transposed: [o][e]
    __shared__ float b1[32];
    __shared__ float b2[16];

    const int tid = threadIdx.x;
    for (int i = tid; i < 512; i += 128) w1[i] = fc1_w[i];
    for (int i = tid; i < 512; i += 128) {
        const int p = i >> 5, o = i & 31;   // fc2_w is [E][2E] row-major
        w2t[o][p] = fc2_w[i];
    }
    if (tid < 32) b1[tid] = fc1_b[tid];
    if (tid < 16) b2[tid] = fc2_b[tid];
    __syncthreads();

    const int HALF = S_LEN / 2;                  // 1536
    const int t    = blockIdx.x * 128 + tid;     // 0 .. 147455
    const int n    = t / (3 * HALF);
    const int r    = t - n * (3 * HALF);
    const int tt   = r / HALF;
    const int posA = r - tt * HALF;
    const int posB = posA + HALF;

    const float* gp = g_params + (long)(n * 3 + tt) * S_LEN * EDIM;

    float pA[16], pB[16];
    if (posA == 0) {
#pragma unroll
        for (int e = 0; e < 16; e++) {
            pA[e] = (tt == 0) ? softplus_f(ind_in_w[e])
                  : (tt == 1) ? ind_in_b[e]
                              : ind_out_w[e];
        }
    } else {
        const float4* src = (const float4*)(gp + (long)(posA - 1) * EDIM);
        const float4 a = src[0], b = src[1], c = src[2], d = src[3];
        pA[0]=a.x; pA[1]=a.y; pA[2]=a.z; pA[3]=a.w;
        pA[4]=b.x; pA[5]=b.y; pA[6]=b.z; pA[7]=b.w;
        pA[8]=c.x; pA[9]=c.y; pA[10]=c.z; pA[11]=c.w;
        pA[12]=d.x; pA[13]=d.y; pA[14]=d.z; pA[15]=d.w;
    }
    {
        const float4* src = (const float4*)(gp + (long)(posB - 1) * EDIM);
        const float4 a = src[0], b = src[1], c = src[2], d = src[3];
        pB[0]=a.x; pB[1]=a.y; pB[2]=a.z; pB[3]=a.w;
        pB[4]=b.x; pB[5]=b.y; pB[6]=b.z; pB[7]=b.w;
        pB[8]=c.x; pB[9]=c.y; pB[10]=c.z; pB[11]=c.w;
        pB[12]=d.x; pB[13]=d.y; pB[14]=d.z; pB[15]=d.w;
    }

    float accA[16], accB[16];
#pragma unroll
    for (int e = 0; e < 16; e++) { accA[e] = b2[e]; accB[e] = b2[e]; }

#pragma unroll
    for (int o = 0; o < 32; o++) {
        const float4* w1p = (const float4*)&w1[o * 16];
        const float4 W0 = w1p[0], W1 = w1p[1], W2 = w1p[2], W3 = w1p[3];
        float hA0 = fmaf(pA[0], W0.x, 0.f),  hA1 = fmaf(pA[1], W0.y, 0.f);
        float hB0 = fmaf(pB[0], W0.x, 0.f),  hB1 = fmaf(pB[1], W0.y, 0.f);
        hA0 = fmaf(pA[2], W0.z, hA0); hA1 = fmaf(pA[3], W0.w, hA1);
        hB0 = fmaf(pB[2], W0.z, hB0); hB1 = fmaf(pB[3], W0.w, hB1);
        hA0 = fmaf(pA[4], W1.x, hA0); hA1 = fmaf(pA[5], W1.y, hA1);
        hB0 = fmaf(pB[4], W1.x, hB0); hB1 = fmaf(pB[5], W1.y, hB1);
        hA0 = fmaf(pA[6], W1.z, hA0); hA1 = fmaf(pA[7], W1.w, hA1);
        hB0 = fmaf(pB[6], W1.z, hB0); hB1 = fmaf(pB[7], W1.w, hB1);
        hA0 = fmaf(pA[8], W2.x, hA0); hA1 = fmaf(pA[9], W2.y, hA1);
        hB0 = fmaf(pB[8], W2.x, hB0); hB1 = fmaf(pB[9], W2.y, hB1);
        hA0 = fmaf(pA[10], W2.z, hA0); hA1 = fmaf(pA[11], W2.w, hA1);
        hB0 = fmaf(pB[10], W2.z, hB0); hB1 = fmaf(pB[11], W2.w, hB1);
        hA0 = fmaf(pA[12], W3.x, hA0); hA1 = fmaf(pA[13], W3.y, hA1);
        hB0 = fmaf(pB[12], W3.x, hB0); hB1 = fmaf(pB[13], W3.y, hB1);
        hA0 = fmaf(pA[14], W3.z, hA0); hA1 = fmaf(pA[15], W3.w, hA1);
        hB0 = fmaf(pB[14], W3.z, hB0); hB1 = fmaf(pB[15], W3.w, hB1);

        const float hA = fmaxf(hA0 + hA1 + b1[o], 0.0f);
        const float hB = fmaxf(hB0 + hB1 + b1[o], 0.0f);

        const float4* w2p = (const float4*)&w2t[o][0];
        const float4 V0 = w2p[0], V1 = w2p[1], V2 = w2p[2], V3 = w2p[3];
        accA[0] = fmaf(hA, V0.x, accA[0]);  accB[0] = fmaf(hB, V0.x, accB[0]);
        accA[1] = fmaf(hA, V0.y, accA[1]);  accB[1] = fmaf(hB, V0.y, accB[1]);
        accA[2] = fmaf(hA, V0.z, accA[2]);  accB[2] = fmaf(hB, V0.z, accB[2]);
        accA[3] = fmaf(hA, V0.w, accA[3]);  accB[3] = fmaf(hB, V0.w, accB[3]);
        accA[4] = fmaf(hA, V1.x, accA[4]);  accB[4] = fmaf(hB, V1.x, accB[4]);
        accA[5] = fmaf(hA, V1.y, accA[5]);  accB[5] = fmaf(hB, V1.y, accB[5]);
        accA[6] = fmaf(hA, V1.z, accA[6]);  accB[6] = fmaf(hB, V1.z, accB[6]);
        accA[7] = fmaf(hA, V1.w, accA[7]);  accB[7] = fmaf(hB, V1.w, accB[7]);
        accA[8] = fmaf(hA, V2.x, accA[8]);  accB[8] = fmaf(hB, V2.x, accB[8]);
        accA[9] = fmaf(hA, V2.y, accA[9]);  accB[9] = fmaf(hB, V2.y, accB[9]);
        accA[10] = fmaf(hA, V2.z, accA[10]); accB[10] = fmaf(hB, V2.z, accB[10]);
        accA[11] = fmaf(hA, V2.w, accA[11]); accB[11] = fmaf(hB, V2.w, accB[11]);
        accA[12] = fmaf(hA, V3.x, accA[12]); accB[12] = fmaf(hB, V3.x, accB[12]);
        accA[13] = fmaf(hA, V3.y, accA[13]); accB[13] = fmaf(hB, V3.y, accB[13]);
        accA[14] = fmaf(hA, V3.z, accA[14]); accB[14] = fmaf(hB, V3.z, accB[14]);
        accA[15] = fmaf(hA, V3.w, accA[15]); accB[15] = fmaf(hB, V3.w, accB[15]);
    }

    if (tt == 0) {   // in_proj_weight gets a final softplus
#pragma unroll
        for (int e = 0; e < 16; e++) {
            accA[e] = softplus_f(accA[e]);
            accB[e] = softplus_f(accB[e]);
        }
    }

    float* dbase = out + ((long)tt * NBATCH + n) * S_LEN * EDIM;
    float4* dA = (float4*)(dbase + (long)posA * EDIM);
    dA[0] = make_float4(accA[0],  accA[1],  accA[2],  accA[3]);
    dA[1] = make_float4(accA[4],  accA[5],  accA[6],  accA[7]);
    dA[2] = make_float4(accA[8],  accA[9],  accA[10], accA[11]);
    dA[3] = make_float4(accA[12], accA[13], accA[14], accA[15]);
    float4* dB = (float4*)(dbase + (long)posB * EDIM);
    dB[0] = make_float4(accB[0],  accB[1],  accB[2],  accB[3]);
    dB[1] = make_float4(accB[4],  accB[5],  accB[6],  accB[7]);
    dB[2] = make_float4(accB[8],  accB[9],  accB[10], accB[11]);
    dB[3] = make_float4(accB[12], accB[13], accB[14], accB[15]);
}

// ---------------------------------------------------------------------------
extern "C" void kernel_launch(void* const* d_in, const int* in_sizes, int n_in,
                              void* d_out, int out_size)
{
    const float* x         = (const float*)d_in[0];
    const float* ew        = (const float*)d_in[1];
    const float* eb        = (const float*)d_in[2];
    const float* ind_in_w  = (const float*)d_in[3];
    const float* ind_in_b  = (const float*)d_in[4];
    const float* ind_out_w = (const float*)d_in[5];
    const float* ind_out_b = (const float*)d_in[6];
    const float* ind_res_w = (const float*)d_in[7];
    const float* fc1_w     = (const float*)d_in[8];
    const float* fc1_b     = (const float*)d_in[9];
    const float* fc2_w     = (const float*)d_in[10];
    const float* fc2_b     = (const float*)d_in[11];
    float* out = (float*)d_out;

    scan_a<<<NHEAD * SPLIT * NPAIR, 256>>>(x, ew, eb);
    scan_b<<<NCHAIN, 272>>>();
    scan_c<<<NHEAD * SPLIT * NPAIR, 256>>>(x, ew, eb, ind_out_b, ind_res_w, out);
    mlp_kernel<<<(NBATCH * 3 * (S_LEN / 2)) / 128, 128>>>(
        ind_in_w, ind_in_b, ind_out_w, fc1_w, fc1_b, fc2_w, fc2_b, out);
}

// round 8
// speedup vs baseline: 1.3109x; 1.0068x over previous
#include <cuda_runtime.h>

#define S_LEN   3072
#define EDIM    16
#define NHEAD   5
#define NBATCH  32
#define NCHAIN  (NBATCH * NHEAD)   // 160
#define SPLIT   8
#define SEG_LEN (S_LEN / SPLIT)    // 384
#define CHUNKS  16
#define CLEN    (SEG_LEN / CHUNKS) // 24
#define NPAIR   (NBATCH / 2)       // 16

// q->k and q->v offsets in float2 units (folded into LDG immediates)
#define KOFF2 (NHEAD * S_LEN * 8)
#define VOFF2 (2 * NHEAD * S_LEN * 8)

// scratch for params of heads 0..2 (inner): [N][3][S_LEN][E]
__device__ float g_params[(long)NBATCH * 3 * S_LEN * EDIM];
// chunk sums -> exclusive prefixes (in-place): [chain*SPLIT+seg][chunk][i][c]
__device__ float g_prefS[(long)NCHAIN * SPLIT * CHUNKS * 256];
__device__ float g_prefZ[(long)NCHAIN * SPLIT * CHUNKS * 16];
__device__ float g_totS [(long)NCHAIN * SPLIT * 256];
__device__ float g_totZ [(long)NCHAIN * SPLIT * 16];

__device__ __forceinline__ float softplus_f(float x) {
    // all args here are small (|x| < ~5): unclamped fast form is exact enough
    return __logf(1.0f + __expf(x));
}

// ---------------------------------------------------------------------------
// K1: batch-paired chunk sums + in-segment exclusive prefix.
// grid = NHEAD*SPLIT*NPAIR = 640, block = 256 = 16 chunks x (2 batches x 8).
// Software-pipelined: position s+1's LDGs issue while s computes.
// ---------------------------------------------------------------------------
__global__ __launch_bounds__(256, 3) void scan_a(
    const float* __restrict__ x,
    const float* __restrict__ ew,
    const float* __restrict__ eb)
{
    __shared__ __align__(16) float kst[2][CHUNKS][2][16];
    __shared__ float sZ[CHUNKS][2][16];

    const int b    = blockIdx.x;
    const int pair = b / (NHEAD * SPLIT);
    const int rem  = b % (NHEAD * SPLIT);
    const int seg  = rem / NHEAD;
    const int head = rem % NHEAD;
    const int tid  = threadIdx.x;
    const int g    = tid >> 4;          // chunk 0..15
    const int sub  = (tid >> 3) & 1;    // batch half
    const int hl   = tid & 7;

    const int n     = pair * 2 + sub;
    const int chain = n * NHEAD + head;
    const float* xw = x + (long)n * S_LEN;
    const int pos0  = seg * SEG_LEN + g * CLEN;

    const long qbase = (long)head * S_LEN * 8 + (long)pos0 * 8 + hl;
    const float2* wq = (const float2*)ew + qbase;
    const float2* bq = (const float2*)eb + qbase;

    float S0[16], S1[16];
#pragma unroll
    for (int i = 0; i < 16; i++) { S0[i] = 0.f; S1[i] = 0.f; }
    float z0 = 0.f, z1 = 0.f;

    // pipeline prologue: loads for s=0
    float  xv = __ldg(xw + pos0);
    float2 ka = __ldg(wq + KOFF2), kc = __ldg(bq + KOFF2);
    float2 va = __ldg(wq + VOFF2), vc = __ldg(bq + VOFF2);

    for (int s = 0; s < CLEN; s++) {
        // prefetch s+1 (clamped on last iter: redundant L1-hit reload)
        const int sn = (s + 1 < CLEN) ? s + 1 : s;
        const float  xvN = __ldg(xw + pos0 + sn);
        const float2 kaN = __ldg(wq + KOFF2 + sn * 8);
        const float2 kcN = __ldg(bq + KOFF2 + sn * 8);
        const float2 vaN = __ldg(wq + VOFF2 + sn * 8);
        const float2 vcN = __ldg(bq + VOFF2 + sn * 8);

        const float kx = softplus_f(fmaf(ka.x, xv, kc.x));
        const float ky = softplus_f(fmaf(ka.y, xv, kc.y));
        const float vx = fmaf(va.x, xv, vc.x);
        const float vy = fmaf(va.y, xv, vc.y);
        z0 += kx; z1 += ky;

        const int buf = s & 1;
        *(float2*)&kst[buf][g][sub][2 * hl] = make_float2(kx, ky);
        __syncwarp();
        const float4* kv = (const float4*)kst[buf][g][sub];
        const float4 K0 = kv[0], K1 = kv[1], K2 = kv[2], K3 = kv[3];
        const float kk[16] = {K0.x,K0.y,K0.z,K0.w, K1.x,K1.y,K1.z,K1.w,
                              K2.x,K2.y,K2.z,K2.w, K3.x,K3.y,K3.z,K3.w};
#pragma unroll
        for (int i = 0; i < 16; i++) {
            S0[i] = fmaf(kk[i], vx, S0[i]);
            S1[i] = fmaf(kk[i], vy, S1[i]);
        }

        xv = xvN; ka = kaN; kc = kcN; va = vaN; vc = vcN;
    }

    // chunk sums -> global ([b][chunk][i][c] layout), z -> smem
    {
        const long pb = ((long)(chain * SPLIT + seg) * CHUNKS + g) * 256;
#pragma unroll
        for (int i = 0; i < 16; i++)
            *(float2*)&g_prefS[pb + i * 16 + 2 * hl] = make_float2(S0[i], S1[i]);
    }
    *(float2*)&sZ[g][sub][2 * hl] = make_float2(z0, z1);
    __syncthreads();

    // in-place exclusive scan over chunks (L2-hot); both batch halves
    {
        const int i = tid >> 4, c = tid & 15;
#pragma unroll
        for (int sub2 = 0; sub2 < 2; sub2++) {
            const int chain2 = (pair * 2 + sub2) * NHEAD + head;
            const long base = ((long)(chain2 * SPLIT + seg) * CHUNKS) * 256
                            + i * 16 + c;
            float run = 0.f;
#pragma unroll
            for (int gg = 0; gg < CHUNKS; gg++) {
                const float t = g_prefS[base + gg * 256];
                g_prefS[base + gg * 256] = run;
                run += t;
            }
            g_totS[(long)(chain2 * SPLIT + seg) * 256 + i * 16 + c] = run;
        }
    }
    if (tid < 32) {
        const int sub2 = tid >> 4, i2 = tid & 15;
        const int chain2 = (pair * 2 + sub2) * NHEAD + head;
        const long bz = (long)(chain2 * SPLIT + seg) * CHUNKS * 16 + i2;
        float rz = 0.f;
#pragma unroll
        for (int gg = 0; gg < CHUNKS; gg++) {
            g_prefZ[bz + gg * 16] = rz;
            rz += sZ[gg][sub2][i2];
        }
        g_totZ[(long)(chain2 * SPLIT + seg) * 16 + i2] = rz;
    }
}

// ---------------------------------------------------------------------------
// K2: exclusive prefix of segment totals across SPLIT segments of each chain
// (in place). grid = 160, block = 272.
// ---------------------------------------------------------------------------
__global__ void scan_b()
{
    const int chain = blockIdx.x;
    const int t = threadIdx.x;
    if (t < 256) {
        float run = 0.f;
#pragma unroll
        for (int s = 0; s < SPLIT; s++) {
            const long idx = ((long)chain * SPLIT + s) * 256 + t;
            const float v = g_totS[idx]; g_totS[idx] = run; run += v;
        }
    } else if (t < 272) {
        const int i = t - 256;
        float run = 0.f;
#pragma unroll
        for (int s = 0; s < SPLIT; s++) {
            const long idx = ((long)chain * SPLIT + s) * 16 + i;
            const float v = g_totZ[idx]; g_totZ[idx] = run; run += v;
        }
    }
}

// ---------------------------------------------------------------------------
// K3: batch-paired rescan from prefix state with q; software-pipelined.
// ---------------------------------------------------------------------------
__global__ __launch_bounds__(256, 3) void scan_c(
    const float* __restrict__ x,
    const float* __restrict__ ew,
    const float* __restrict__ eb,
    const float* __restrict__ ind_out_b,
    const float* __restrict__ ind_res_w,
    float* __restrict__ out)
{
    __shared__ __align__(16) float st[2][CHUNKS][2][32];  // [buf][chunk][sub][k|q]

    const int b    = blockIdx.x;
    const int pair = b / (NHEAD * SPLIT);
    const int rem  = b % (NHEAD * SPLIT);
    const int seg  = rem / NHEAD;
    const int head = rem % NHEAD;
    const int tid  = threadIdx.x;
    const int g    = tid >> 4;
    const int sub  = (tid >> 3) & 1;
    const int hl   = tid & 7;

    const int n     = pair * 2 + sub;
    const int chain = n * NHEAD + head;
    const float* xw = x + (long)n * S_LEN;
    const int pos0  = seg * SEG_LEN + g * CLEN;

    const long qbase = (long)head * S_LEN * 8 + (long)pos0 * 8 + hl;
    const float2* wq = (const float2*)ew + qbase;
    const float2* bq = (const float2*)eb + qbase;

    // prefix state = chunk prefix + exclusive segment total
    float S0[16], S1[16], z0, z1;
    {
        const long pb = ((long)(chain * SPLIT + seg) * CHUNKS + g) * 256;
        const long tb = (long)(chain * SPLIT + seg) * 256;
#pragma unroll
        for (int i = 0; i < 16; i++) {
            const float2 p = *(const float2*)&g_prefS[pb + i * 16 + 2 * hl];
            const float2 t = *(const float2*)&g_totS[tb + i * 16 + 2 * hl];
            S0[i] = p.x + t.x; S1[i] = p.y + t.y;
        }
        const float2 pz = *(const float2*)&g_prefZ[
            ((long)(chain * SPLIT + seg) * CHUNKS + g) * 16 + 2 * hl];
        const float2 tz = *(const float2*)&g_totZ[
            (long)(chain * SPLIT + seg) * 16 + 2 * hl];
        z0 = pz.x + tz.x; z1 = pz.y + tz.y;
    }

    const bool isInner = (head < 3);
    float* pdst = nullptr;
    float* odst = nullptr;
    if (isInner) {
        pdst = g_params + ((long)(n * 3 + head) * S_LEN) * EDIM;
    } else {
        const long base = (long)3 * NBATCH * S_LEN * EDIM
                        + (long)(head - 3) * NBATCH * S_LEN;
        odst = out + base + (long)n * S_LEN;
        if (g == 0 && hl == 0 && seg == 0)
            odst[0] = (head == 3) ? ind_out_b[0] : ind_res_w[0];
    }

    // pipeline prologue: loads for s=0
    float  xv = __ldg(xw + pos0);
    float2 qa = __ldg(wq),         qc = __ldg(bq);
    float2 ka = __ldg(wq + KOFF2), kc = __ldg(bq + KOFF2);
    float2 va = __ldg(wq + VOFF2), vc = __ldg(bq + VOFF2);

    for (int s = 0; s < CLEN; s++) {
        const int sn = (s + 1 < CLEN) ? s + 1 : s;
        const float  xvN = __ldg(xw + pos0 + sn);
        const float2 qaN = __ldg(wq + sn * 8);
        const float2 qcN = __ldg(bq + sn * 8);
        const float2 kaN = __ldg(wq + KOFF2 + sn * 8);
        const float2 kcN = __ldg(bq + KOFF2 + sn * 8);
        const float2 vaN = __ldg(wq + VOFF2 + sn * 8);
        const float2 vcN = __ldg(bq + VOFF2 + sn * 8);

        const int pos = pos0 + s;
        const float qx = softplus_f(fmaf(qa.x, xv, qc.x));
        const float qy = softplus_f(fmaf(qa.y, xv, qc.y));
        const float kx = softplus_f(fmaf(ka.x, xv, kc.x));
        const float ky = softplus_f(fmaf(ka.y, xv, kc.y));
        const float vx = fmaf(va.x, xv, vc.x);
        const float vy = fmaf(va.y, xv, vc.y);

        z0 += kx; z1 += ky;

        const int buf = s & 1;
        *(float2*)&st[buf][g][sub][2 * hl]      = make_float2(kx, ky);
        *(float2*)&st[buf][g][sub][16 + 2 * hl] = make_float2(qx, qy);
        __syncwarp();

        float dp = fmaf(qx, z0, qy * z1);
        dp += __shfl_xor_sync(0xffffffffu, dp, 1, 8);
        dp += __shfl_xor_sync(0xffffffffu, dp, 2, 8);
        dp += __shfl_xor_sync(0xffffffffu, dp, 4, 8);

        const float4* kv = (const float4*)&st[buf][g][sub][0];
        const float4* qv = (const float4*)&st[buf][g][sub][16];
        float num0 = 0.f, num1 = 0.f;
#pragma unroll
        for (int q4 = 0; q4 < 4; q4++) {
            const float4 K = kv[q4];
            const float4 Q = qv[q4];
            S0[4*q4+0] = fmaf(K.x, vx, S0[4*q4+0]); num0 = fmaf(Q.x, S0[4*q4+0], num0);
            S0[4*q4+1] = fmaf(K.y, vx, S0[4*q4+1]); num0 = fmaf(Q.y, S0[4*q4+1], num0);
            S0[4*q4+2] = fmaf(K.z, vx, S0[4*q4+2]); num0 = fmaf(Q.z, S0[4*q4+2], num0);
            S0[4*q4+3] = fmaf(K.w, vx, S0[4*q4+3]); num0 = fmaf(Q.w, S0[4*q4+3], num0);
            S1[4*q4+0] = fmaf(K.x, vy, S1[4*q4+0]); num1 = fmaf(Q.x, S1[4*q4+0], num1);
            S1[4*q4+1] = fmaf(K.y, vy, S1[4*q4+1]); num1 = fmaf(Q.y, S1[4*q4+1], num1);
            S1[4*q4+2] = fmaf(K.z, vy, S1[4*q4+2]); num1 = fmaf(Q.z, S1[4*q4+2], num1);
            S1[4*q4+3] = fmaf(K.w, vy, S1[4*q4+3]); num1 = fmaf(Q.w, S1[4*q4+3], num1);
        }
        const float r = __fdividef(1.0f, dp);
        const float p0 = num0 * r, p1 = num1 * r;

        if (isInner) {
            *(float2*)&pdst[(long)pos * EDIM + 2 * hl] = make_float2(p0, p1);
        } else {
            float tot = p0 + p1;
            tot += __shfl_xor_sync(0xffffffffu, tot, 1, 8);
            tot += __shfl_xor_sync(0xffffffffu, tot, 2, 8);
            tot += __shfl_xor_sync(0xffffffffu, tot, 4, 8);
            if (hl == 0 && pos + 1 < S_LEN)
                odst[pos + 1] = tot;
        }

        xv = xvN; qa = qaN; qc = qcN; ka = kaN; kc = kcN; va = vaN; vc = vcN;
    }
}

// ---------------------------------------------------------------------------
// K4: per-position MLP for heads 0..2 on shifted params.
// 1 position/thread, 64-reg cap -> 50% occupancy.
// ---------------------------------------------------------------------------
__global__ __launch_bounds__(256, 4) void mlp_kernel(
    const float* __restrict__ ind_in_w,
    const float* __restrict__ ind_in_b,
    const float* __restrict__ ind_out_w,
    const float* __restrict__ fc1_w,
    const float* __restrict__ fc1_b,
    const float* __restrict__ fc2_w,
    const float* __restrict__ fc2_b,
    float* __restrict__ out)
{
    __shared__ __align__(16) float w1[32 * 16];
    __shared__ __align__(16) float w2t[32][16];   // transposed: [o][e]
    __shared__ float b1[32];
    __shared__ float b2[16];

    const int tid = threadIdx.x;
    for (int i = tid; i < 512; i += 256) w1[i] = fc1_w[i];
    for (int i = tid; i < 512; i += 256) {
        const int p = i >> 5, o = i & 31;   // fc2_w is [E][2E] row-major
        w2t[o][p] = fc2_w[i];
    }
    if (tid < 32) b1[tid] = fc1_b[tid];
    if (tid < 16) b2[tid] = fc2_b[tid];
    __syncthreads();

    const int t   = blockIdx.x * 256 + tid;      // 0 .. 294911
    const int n   = t / (3 * S_LEN);
    const int r   = t - n * (3 * S_LEN);
    const int tt  = r / S_LEN;
    const int pos = r - tt * S_LEN;

    float4 P0, P1, P2, P3;
    if (pos == 0) {
        float p[16];
#pragma unroll
        for (int e = 0; e < 16; e++) {
            p[e] = (tt == 0) ? softplus_f(ind_in_w[e])
                 : (tt == 1) ? ind_in_b[e]
                             : ind_out_w[e];
        }
        P0 = make_float4(p[0], p[1], p[2], p[3]);
        P1 = make_float4(p[4], p[5], p[6], p[7]);
        P2 = make_float4(p[8], p[9], p[10], p[11]);
        P3 = make_float4(p[12], p[13], p[14], p[15]);
    } else {
        const float4* src = (const float4*)(g_params
            + ((long)(n * 3 + tt) * S_LEN + (pos - 1)) * EDIM);
        P0 = src[0]; P1 = src[1]; P2 = src[2]; P3 = src[3];
    }

    float4 A0, A1, A2, A3;
    A0 = make_float4(b2[0], b2[1], b2[2], b2[3]);
    A1 = make_float4(b2[4], b2[5], b2[6], b2[7]);
    A2 = make_float4(b2[8], b2[9], b2[10], b2[11]);
    A3 = make_float4(b2[12], b2[13], b2[14], b2[15]);

#pragma unroll
    for (int o = 0; o < 32; o++) {
        const float4* w1p = (const float4*)&w1[o * 16];
        float h0, h1;
        {
            const float4 W = w1p[0];
            h0 = fmaf(P0.x, W.x, 0.f);  h1 = fmaf(P0.y, W.y, 0.f);
            h0 = fmaf(P0.z, W.z, h0);   h1 = fmaf(P0.w, W.w, h1);
        }
        {
            const float4 W = w1p[1];
            h0 = fmaf(P1.x, W.x, h0);   h1 = fmaf(P1.y, W.y, h1);
            h0 = fmaf(P1.z, W.z, h0);   h1 = fmaf(P1.w, W.w, h1);
        }
        {
            const float4 W = w1p[2];
            h0 = fmaf(P2.x, W.x, h0);   h1 = fmaf(P2.y, W.y, h1);
            h0 = fmaf(P2.z, W.z, h0);   h1 = fmaf(P2.w, W.w, h1);
        }
        {
            const float4 W = w1p[3];
            h0 = fmaf(P3.x, W.x, h0);   h1 = fmaf(P3.y, W.y, h1);
            h0 = fmaf(P3.z, W.z, h0);   h1 = fmaf(P3.w, W.w, h1);
        }
        const float h = fmaxf(h0 + h1 + b1[o], 0.0f);

        const float4* w2p = (const float4*)&w2t[o][0];
        {
            const float4 V = w2p[0];
            A0.x = fmaf(h, V.x, A0.x); A0.y = fmaf(h, V.y, A0.y);
            A0.z = fmaf(h, V.z, A0.z); A0.w = fmaf(h, V.w, A0.w);
        }
        {
            const float4 V = w2p[1];
            A1.x = fmaf(h, V.x, A1.x); A1.y = fmaf(h, V.y, A1.y);
            A1.z = fmaf(h, V.z, A1.z); A1.w = fmaf(h, V.w, A1.w);
        }
        {
            const float4 V = w2p[2];
            A2.x = fmaf(h, V.x, A2.x); A2.y = fmaf(h, V.y, A2.y);
            A2.z = fmaf(h, V.z, A2.z); A2.w = fmaf(h, V.w, A2.w);
        }
        {
            const float4 V = w2p[3];
            A3.x = fmaf(h, V.x, A3.x); A3.y = fmaf(h, V.y, A3.y);
            A3.z = fmaf(h, V.z, A3.z); A3.w = fmaf(h, V.w, A3.w);
        }
    }

    if (tt == 0) {   // in_proj_weight gets a final softplus
        A0.x = softplus_f(A0.x); A0.y = softplus_f(A0.y);
        A0.z = softplus_f(A0.z); A0.w = softplus_f(A0.w);
        A1.x = softplus_f(A1.x); A1.y = softplus_f(A1.y);
        A1.z = softplus_f(A1.z); A1.w = softplus_f(A1.w);
        A2.x = softplus_f(A2.x); A2.y = softplus_f(A2.y);
        A2.z = softplus_f(A2.z); A2.w = softplus_f(A2.w);
        A3.x = softplus_f(A3.x); A3.y = softplus_f(A3.y);
        A3.z = softplus_f(A3.z); A3.w = softplus_f(A3.w);
    }

    float4* dst = (float4*)(out
        + ((long)tt * NBATCH + n) * S_LEN * EDIM + (long)pos * EDIM);
    dst[0] = A0; dst[1] = A1; dst[2] = A2; dst[3] = A3;
}

// ---------------------------------------------------------------------------
extern "C" void kernel_launch(void* const* d_in, const int* in_sizes, int n_in,
                              void* d_out, int out_size)
{
    const float* x         = (const float*)d_in[0];
    const float* ew        = (const float*)d_in[1];
    const float* eb        = (const float*)d_in[2];
    const float* ind_in_w  = (const float*)d_in[3];
    const float* ind_in_b  = (const float*)d_in[4];
    const float* ind_out_w = (const float*)d_in[5];
    const float* ind_out_b = (const float*)d_in[6];
    const float* ind_res_w = (const float*)d_in[7];
    const float* fc1_w     = (const float*)d_in[8];
    const float* fc1_b     = (const float*)d_in[9];
    const float* fc2_w     = (const float*)d_in[10];
    const float* fc2_b     = (const float*)d_in[11];
    float* out = (float*)d_out;

    scan_a<<<NHEAD * SPLIT * NPAIR, 256>>>(x, ew, eb);
    scan_b<<<NCHAIN, 272>>>();
    scan_c<<<NHEAD * SPLIT * NPAIR, 256>>>(x, ew, eb, ind_out_b, ind_res_w, out);
    mlp_kernel<<<(NBATCH * 3 * S_LEN) / 256, 256>>>(
        ind_in_w, ind_in_b, ind_out_w, fc1_w, fc1_b, fc2_w, fc2_b, out);
}

// round 9
// speedup vs baseline: 1.3563x; 1.0346x over previous
#include <cuda_runtime.h>

#define S_LEN   3072
#define EDIM    16
#define NHEAD   5
#define NBATCH  32
#define NCHAIN  (NBATCH * NHEAD)   // 160
#define SPLIT   16
#define SEG_LEN (S_LEN / SPLIT)    // 192
#define CHUNKS  8
#define CLEN    (SEG_LEN / CHUNKS) // 24
#define NQUAD   (NBATCH / 4)       // 8

// q->k and q->v offsets in float2 units (folded into LDG immediates)
#define KOFF2 (NHEAD * S_LEN * 8)
#define VOFF2 (2 * NHEAD * S_LEN * 8)

// scratch for params of heads 0..2 (inner): [N][3][S_LEN][E]
__device__ float g_params[(long)NBATCH * 3 * S_LEN * EDIM];
// chunk sums -> exclusive prefixes (in-place): [chain*SPLIT+seg][chunk][i][c]
__device__ float g_prefS[(long)NCHAIN * SPLIT * CHUNKS * 256];
__device__ float g_prefZ[(long)NCHAIN * SPLIT * CHUNKS * 16];
__device__ float g_totS [(long)NCHAIN * SPLIT * 256];
__device__ float g_totZ [(long)NCHAIN * SPLIT * 16];

__device__ __forceinline__ float softplus_f(float x) {
    // all args here are small (|x| < ~5): unclamped fast form is exact enough
    return __logf(1.0f + __expf(x));
}

// ---------------------------------------------------------------------------
// K1: batch-quad chunk sums + in-segment exclusive prefix.
// grid = NQUAD*SPLIT*NHEAD = 640, block = 256 = 8 chunks x (4 batches x 8).
// One warp = 1 chunk x 4 batches: all 32 lanes read the SAME 64B weight
// region per array -> 1 L1 wavefront per weight LDG serving 4 batches.
// ---------------------------------------------------------------------------
__global__ __launch_bounds__(256, 3) void scan_a(
    const float* __restrict__ x,
    const float* __restrict__ ew,
    const float* __restrict__ eb)
{
    __shared__ __align__(16) float kst[2][CHUNKS][4][16];
    __shared__ float sZ[CHUNKS][4][16];

    const int b    = blockIdx.x;
    const int quad = b / (NHEAD * SPLIT);
    const int rem  = b % (NHEAD * SPLIT);
    const int seg  = rem / NHEAD;
    const int head = rem % NHEAD;
    const int tid  = threadIdx.x;
    const int g    = tid >> 5;          // chunk 0..7
    const int sub  = (tid >> 3) & 3;    // batch within quad
    const int hl   = tid & 7;

    const int n     = quad * 4 + sub;
    const int chain = n * NHEAD + head;
    const float* xw = x + (long)n * S_LEN;
    const int pos0  = seg * SEG_LEN + g * CLEN;

    const long qbase = (long)head * S_LEN * 8 + (long)pos0 * 8 + hl;
    const float2* wq = (const float2*)ew + qbase;
    const float2* bq = (const float2*)eb + qbase;

    float S0[16], S1[16];
#pragma unroll
    for (int i = 0; i < 16; i++) { S0[i] = 0.f; S1[i] = 0.f; }
    float z0 = 0.f, z1 = 0.f;

    for (int s = 0; s < CLEN; s++) {
        const float xv = __ldg(xw + pos0 + s);
        const float2 a  = __ldg(wq + KOFF2 + s * 8);
        const float2 bb = __ldg(bq + KOFF2 + s * 8);
        const float kx = softplus_f(fmaf(a.x, xv, bb.x));
        const float ky = softplus_f(fmaf(a.y, xv, bb.y));
        const float2 c  = __ldg(wq + VOFF2 + s * 8);
        const float2 d  = __ldg(bq + VOFF2 + s * 8);
        const float vx = fmaf(c.x, xv, d.x);
        const float vy = fmaf(c.y, xv, d.y);
        z0 += kx; z1 += ky;

        const int buf = s & 1;
        *(float2*)&kst[buf][g][sub][2 * hl] = make_float2(kx, ky);
        __syncwarp();
        const float4* kv = (const float4*)kst[buf][g][sub];
        const float4 K0 = kv[0], K1 = kv[1], K2 = kv[2], K3 = kv[3];
        const float kk[16] = {K0.x,K0.y,K0.z,K0.w, K1.x,K1.y,K1.z,K1.w,
                              K2.x,K2.y,K2.z,K2.w, K3.x,K3.y,K3.z,K3.w};
#pragma unroll
        for (int i = 0; i < 16; i++) {
            S0[i] = fmaf(kk[i], vx, S0[i]);
            S1[i] = fmaf(kk[i], vy, S1[i]);
        }
    }

    // chunk sums -> global ([b][chunk][i][c] layout), z -> smem
    {
        const long pb = ((long)(chain * SPLIT + seg) * CHUNKS + g) * 256;
#pragma unroll
        for (int i = 0; i < 16; i++)
            *(float2*)&g_prefS[pb + i * 16 + 2 * hl] = make_float2(S0[i], S1[i]);
    }
    *(float2*)&sZ[g][sub][2 * hl] = make_float2(z0, z1);
    __syncthreads();

    // in-place exclusive scan over chunks (L2-hot); all 4 batch subs
    {
        const int i = tid >> 4, c = tid & 15;
#pragma unroll
        for (int sub2 = 0; sub2 < 4; sub2++) {
            const int chain2 = (quad * 4 + sub2) * NHEAD + head;
            const long base = ((long)(chain2 * SPLIT + seg) * CHUNKS) * 256
                            + i * 16 + c;
            float run = 0.f;
#pragma unroll
            for (int gg = 0; gg < CHUNKS; gg++) {
                const float t = g_prefS[base + gg * 256];
                g_prefS[base + gg * 256] = run;
                run += t;
            }
            g_totS[(long)(chain2 * SPLIT + seg) * 256 + i * 16 + c] = run;
        }
    }
    if (tid < 64) {
        const int sub2 = (tid >> 4) & 3, i2 = tid & 15;
        const int chain2 = (quad * 4 + sub2) * NHEAD + head;
        const long bz = (long)(chain2 * SPLIT + seg) * CHUNKS * 16 + i2;
        float rz = 0.f;
#pragma unroll
        for (int gg = 0; gg < CHUNKS; gg++) {
            g_prefZ[bz + gg * 16] = rz;
            rz += sZ[gg][sub2][i2];
        }
        g_totZ[(long)(chain2 * SPLIT + seg) * 16 + i2] = rz;
    }
}

// ---------------------------------------------------------------------------
// K2: exclusive prefix of segment totals across SPLIT segments of each chain
// (in place). grid = 160, block = 272.
// ---------------------------------------------------------------------------
__global__ void scan_b()
{
    const int chain = blockIdx.x;
    const int t = threadIdx.x;
    if (t < 256) {
        float run = 0.f;
#pragma unroll
        for (int s = 0; s < SPLIT; s++) {
            const long idx = ((long)chain * SPLIT + s) * 256 + t;
            const float v = g_totS[idx]; g_totS[idx] = run; run += v;
        }
    } else if (t < 272) {
        const int i = t - 256;
        float run = 0.f;
#pragma unroll
        for (int s = 0; s < SPLIT; s++) {
            const long idx = ((long)chain * SPLIT + s) * 16 + i;
            const float v = g_totZ[idx]; g_totZ[idx] = run; run += v;
        }
    }
}

// ---------------------------------------------------------------------------
// K3: batch-quad rescan from prefix state with q; emit params (heads 0-2 ->
// scratch) or e-summed shifted outputs (heads 3-4 -> d_out).
// ---------------------------------------------------------------------------
__global__ __launch_bounds__(256, 3) void scan_c(
    const float* __restrict__ x,
    const float* __restrict__ ew,
    const float* __restrict__ eb,
    const float* __restrict__ ind_out_b,
    const float* __restrict__ ind_res_w,
    float* __restrict__ out)
{
    __shared__ __align__(16) float st[2][CHUNKS][4][32];  // [buf][chunk][sub][k|q]

    const int b    = blockIdx.x;
    const int quad = b / (NHEAD * SPLIT);
    const int rem  = b % (NHEAD * SPLIT);
    const int seg  = rem / NHEAD;
    const int head = rem % NHEAD;
    const int tid  = threadIdx.x;
    const int g    = tid >> 5;
    const int sub  = (tid >> 3) & 3;
    const int hl   = tid & 7;

    const int n     = quad * 4 + sub;
    const int chain = n * NHEAD + head;
    const float* xw = x + (long)n * S_LEN;
    const int pos0  = seg * SEG_LEN + g * CLEN;

    const long qbase = (long)head * S_LEN * 8 + (long)pos0 * 8 + hl;
    const float2* wq = (const float2*)ew + qbase;
    const float2* bq = (const float2*)eb + qbase;

    // prefix state = chunk prefix + exclusive segment total
    float S0[16], S1[16], z0, z1;
    {
        const long pb = ((long)(chain * SPLIT + seg) * CHUNKS + g) * 256;
        const long tb = (long)(chain * SPLIT + seg) * 256;
#pragma unroll
        for (int i = 0; i < 16; i++) {
            const float2 p = *(const float2*)&g_prefS[pb + i * 16 + 2 * hl];
            const float2 t = *(const float2*)&g_totS[tb + i * 16 + 2 * hl];
            S0[i] = p.x + t.x; S1[i] = p.y + t.y;
        }
        const float2 pz = *(const float2*)&g_prefZ[
            ((long)(chain * SPLIT + seg) * CHUNKS + g) * 16 + 2 * hl];
        const float2 tz = *(const float2*)&g_totZ[
            (long)(chain * SPLIT + seg) * 16 + 2 * hl];
        z0 = pz.x + tz.x; z1 = pz.y + tz.y;
    }

    const bool isInner = (head < 3);
    float* pdst = nullptr;
    float* odst = nullptr;
    if (isInner) {
        pdst = g_params + ((long)(n * 3 + head) * S_LEN) * EDIM;
    } else {
        const long base = (long)3 * NBATCH * S_LEN * EDIM
                        + (long)(head - 3) * NBATCH * S_LEN;
        odst = out + base + (long)n * S_LEN;
        if (g == 0 && hl == 0 && seg == 0)
            odst[0] = (head == 3) ? ind_out_b[0] : ind_res_w[0];
    }

    for (int s = 0; s < CLEN; s++) {
        const int pos = pos0 + s;
        const float xv = __ldg(xw + pos);
        float2 a, c;
        a = __ldg(wq + s * 8);         c = __ldg(bq + s * 8);
        const float qx = softplus_f(fmaf(a.x, xv, c.x));
        const float qy = softplus_f(fmaf(a.y, xv, c.y));
        a = __ldg(wq + KOFF2 + s * 8); c = __ldg(bq + KOFF2 + s * 8);
        const float kx = softplus_f(fmaf(a.x, xv, c.x));
        const float ky = softplus_f(fmaf(a.y, xv, c.y));
        a = __ldg(wq + VOFF2 + s * 8); c = __ldg(bq + VOFF2 + s * 8);
        const float vx = fmaf(a.x, xv, c.x);
        const float vy = fmaf(a.y, xv, c.y);

        z0 += kx; z1 += ky;

        const int buf = s & 1;
        *(float2*)&st[buf][g][sub][2 * hl]      = make_float2(kx, ky);
        *(float2*)&st[buf][g][sub][16 + 2 * hl] = make_float2(qx, qy);
        __syncwarp();

        float dp = fmaf(qx, z0, qy * z1);
        dp += __shfl_xor_sync(0xffffffffu, dp, 1, 8);
        dp += __shfl_xor_sync(0xffffffffu, dp, 2, 8);
        dp += __shfl_xor_sync(0xffffffffu, dp, 4, 8);

        const float4* kv = (const float4*)&st[buf][g][sub][0];
        const float4* qv = (const float4*)&st[buf][g][sub][16];
        float num0 = 0.f, num1 = 0.f;
#pragma unroll
        for (int q4 = 0; q4 < 4; q4++) {
            const float4 K = kv[q4];
            const float4 Q = qv[q4];
            S0[4*q4+0] = fmaf(K.x, vx, S0[4*q4+0]); num0 = fmaf(Q.x, S0[4*q4+0], num0);
            S0[4*q4+1] = fmaf(K.y, vx, S0[4*q4+1]); num0 = fmaf(Q.y, S0[4*q4+1], num0);
            S0[4*q4+2] = fmaf(K.z, vx, S0[4*q4+2]); num0 = fmaf(Q.z, S0[4*q4+2], num0);
            S0[4*q4+3] = fmaf(K.w, vx, S0[4*q4+3]); num0 = fmaf(Q.w, S0[4*q4+3], num0);
            S1[4*q4+0] = fmaf(K.x, vy, S1[4*q4+0]); num1 = fmaf(Q.x, S1[4*q4+0], num1);
            S1[4*q4+1] = fmaf(K.y, vy, S1[4*q4+1]); num1 = fmaf(Q.y, S1[4*q4+1], num1);
            S1[4*q4+2] = fmaf(K.z, vy, S1[4*q4+2]); num1 = fmaf(Q.z, S1[4*q4+2], num1);
            S1[4*q4+3] = fmaf(K.w, vy, S1[4*q4+3]); num1 = fmaf(Q.w, S1[4*q4+3], num1);
        }
        const float r = __fdividef(1.0f, dp);
        const float p0 = num0 * r, p1 = num1 * r;

        if (isInner) {
            *(float2*)&pdst[(long)pos * EDIM + 2 * hl] = make_float2(p0, p1);
        } else {
            float tot = p0 + p1;
            tot += __shfl_xor_sync(0xffffffffu, tot, 1, 8);
            tot += __shfl_xor_sync(0xffffffffu, tot, 2, 8);
            tot += __shfl_xor_sync(0xffffffffu, tot, 4, 8);
            if (hl == 0 && pos + 1 < S_LEN)
                odst[pos + 1] = tot;
        }
    }
}

// ---------------------------------------------------------------------------
// K4: per-position MLP for heads 0..2 on shifted params.
// 2 positions per thread (pos, pos+1536) sharing every weight load.
// (R7-measured 30.6us variant, restored verbatim.)
// ---------------------------------------------------------------------------
__global__ __launch_bounds__(128) void mlp_kernel(
    const float* __restrict__ ind_in_w,
    const float* __restrict__ ind_in_b,
    const float* __restrict__ ind_out_w,
    const float* __restrict__ fc1_w,
    const float* __restrict__ fc1_b,
    const float* __restrict__ fc2_w,
    const float* __restrict__ fc2_b,
    float* __restrict__ out)
{
    __shared__ __align__(16) float w1[32 * 16];
    __shared__ __align__(16) float w2t[32][16];   // transposed: [o][e]
    __shared__ float b1[32];
    __shared__ float b2[16];

    const int tid = threadIdx.x;
    for (int i = tid; i < 512; i += 128) w1[i] = fc1_w[i];
    for (int i = tid; i < 512; i += 128) {
        const int p = i >> 5, o = i & 31;   // fc2_w is [E][2E] row-major
        w2t[o][p] = fc2_w[i];
    }
    if (tid < 32) b1[tid] = fc1_b[tid];
    if (tid < 16) b2[tid] = fc2_b[tid];
    __syncthreads();

    const int HALF = S_LEN / 2;                  // 1536
    const int t    = blockIdx.x * 128 + tid;     // 0 .. 147455
    const int n    = t / (3 * HALF);
    const int r    = t - n * (3 * HALF);
    const int tt   = r / HALF;
    const int posA = r - tt * HALF;
    const int posB = posA + HALF;

    const float* gp = g_params + (long)(n * 3 + tt) * S_LEN * EDIM;

    float pA[16], pB[16];
    if (posA == 0) {
#pragma unroll
        for (int e = 0; e < 16; e++) {
            pA[e] = (tt == 0) ? softplus_f(ind_in_w[e])
                  : (tt == 1) ? ind_in_b[e]
                              : ind_out_w[e];
        }
    } else {
        const float4* src = (const float4*)(gp + (long)(posA - 1) * EDIM);
        const float4 a = src[0], b = src[1], c = src[2], d = src[3];
        pA[0]=a.x; pA[1]=a.y; pA[2]=a.z; pA[3]=a.w;
        pA[4]=b.x; pA[5]=b.y; pA[6]=b.z; pA[7]=b.w;
        pA[8]=c.x; pA[9]=c.y; pA[10]=c.z; pA[11]=c.w;
        pA[12]=d.x; pA[13]=d.y; pA[14]=d.z; pA[15]=d.w;
    }
    {
        const float4* src = (const float4*)(gp + (long)(posB - 1) * EDIM);
        const float4 a = src[0], b = src[1], c = src[2], d = src[3];
        pB[0]=a.x; pB[1]=a.y; pB[2]=a.z; pB[3]=a.w;
        pB[4]=b.x; pB[5]=b.y; pB[6]=b.z; pB[7]=b.w;
        pB[8]=c.x; pB[9]=c.y; pB[10]=c.z; pB[11]=c.w;
        pB[12]=d.x; pB[13]=d.y; pB[14]=d.z; pB[15]=d.w;
    }

    float accA[16], accB[16];
#pragma unroll
    for (int e = 0; e < 16; e++) { accA[e] = b2[e]; accB[e] = b2[e]; }

#pragma unroll
    for (int o = 0; o < 32; o++) {
        const float4* w1p = (const float4*)&w1[o * 16];
        const float4 W0 = w1p[0], W1 = w1p[1], W2 = w1p[2], W3 = w1p[3];
        float hA0 = fmaf(pA[0], W0.x, 0.f),  hA1 = fmaf(pA[1], W0.y, 0.f);
        float hB0 = fmaf(pB[0], W0.x, 0.f),  hB1 = fmaf(pB[1], W0.y, 0.f);
        hA0 = fmaf(pA[2], W0.z, hA0); hA1 = fmaf(pA[3], W0.w, hA1);
        hB0 = fmaf(pB[2], W0.z, hB0); hB1 = fmaf(pB[3], W0.w, hB1);
        hA0 = fmaf(pA[4], W1.x, hA0); hA1 = fmaf(pA[5], W1.y, hA1);
        hB0 = fmaf(pB[4], W1.x, hB0); hB1 = fmaf(pB[5], W1.y, hB1);
        hA0 = fmaf(pA[6], W1.z, hA0); hA1 = fmaf(pA[7], W1.w, hA1);
        hB0 = fmaf(pB[6], W1.z, hB0); hB1 = fmaf(pB[7], W1.w, hB1);
        hA0 = fmaf(pA[8], W2.x, hA0); hA1 = fmaf(pA[9], W2.y, hA1);
        hB0 = fmaf(pB[8], W2.x, hB0); hB1 = fmaf(pB[9], W2.y, hB1);
        hA0 = fmaf(pA[10], W2.z, hA0); hA1 = fmaf(pA[11], W2.w, hA1);
        hB0 = fmaf(pB[10], W2.z, hB0); hB1 = fmaf(pB[11], W2.w, hB1);
        hA0 = fmaf(pA[12], W3.x, hA0); hA1 = fmaf(pA[13], W3.y, hA1);
        hB0 = fmaf(pB[12], W3.x, hB0); hB1 = fmaf(pB[13], W3.y, hB1);
        hA0 = fmaf(pA[14], W3.z, hA0); hA1 = fmaf(pA[15], W3.w, hA1);
        hB0 = fmaf(pB[14], W3.z, hB0); hB1 = fmaf(pB[15], W3.w, hB1);

        const float hA = fmaxf(hA0 + hA1 + b1[o], 0.0f);
        const float hB = fmaxf(hB0 + hB1 + b1[o], 0.0f);

        const float4* w2p = (const float4*)&w2t[o][0];
        const float4 V0 = w2p[0], V1 = w2p[1], V2 = w2p[2], V3 = w2p[3];
        accA[0] = fmaf(hA, V0.x, accA[0]);  accB[0] = fmaf(hB, V0.x, accB[0]);
        accA[1] = fmaf(hA, V0.y, accA[1]);  accB[1] = fmaf(hB, V0.y, accB[1]);
        accA[2] = fmaf(hA, V0.z, accA[2]);  accB[2] = fmaf(hB, V0.z, accB[2]);
        accA[3] = fmaf(hA, V0.w, accA[3]);  accB[3] = fmaf(hB, V0.w, accB[3]);
        accA[4] = fmaf(hA, V1.x, accA[4]);  accB[4] = fmaf(hB, V1.x, accB[4]);
        accA[5] = fmaf(hA, V1.y, accA[5]);  accB[5] = fmaf(hB, V1.y, accB[5]);
        accA[6] = fmaf(hA, V1.z, accA[6]);  accB[6] = fmaf(hB, V1.z, accB[6]);
        accA[7] = fmaf(hA, V1.w, accA[7]);  accB[7] = fmaf(hB, V1.w, accB[7]);
        accA[8] = fmaf(hA, V2.x, accA[8]);  accB[8] = fmaf(hB, V2.x, accB[8]);
        accA[9] = fmaf(hA, V2.y, accA[9]);  accB[9] = fmaf(hB, V2.y, accB[9]);
        accA[10] = fmaf(hA, V2.z, accA[10]); accB[10] = fmaf(hB, V2.z, accB[10]);
        accA[11] = fmaf(hA, V2.w, accA[11]); accB[11] = fmaf(hB, V2.w, accB[11]);
        accA[12] = fmaf(hA, V3.x, accA[12]); accB[12] = fmaf(hB, V3.x, accB[12]);
        accA[13] = fmaf(hA, V3.y, accA[13]); accB[13] = fmaf(hB, V3.y, accB[13]);
        accA[14] = fmaf(hA, V3.z, accA[14]); accB[14] = fmaf(hB, V3.z, accB[14]);
        accA[15] = fmaf(hA, V3.w, accA[15]); accB[15] = fmaf(hB, V3.w, accB[15]);
    }

    if (tt == 0) {   // in_proj_weight gets a final softplus
#pragma unroll
        for (int e = 0; e < 16; e++) {
            accA[e] = softplus_f(accA[e]);
            accB[e] = softplus_f(accB[e]);
        }
    }

    float* dbase = out + ((long)tt * NBATCH + n) * S_LEN * EDIM;
    float4* dA = (float4*)(dbase + (long)posA * EDIM);
    dA[0] = make_float4(accA[0],  accA[1],  accA[2],  accA[3]);
    dA[1] = make_float4(accA[4],  accA[5],  accA[6],  accA[7]);
    dA[2] = make_float4(accA[8],  accA[9],  accA[10], accA[11]);
    dA[3] = make_float4(accA[12], accA[13], accA[14], accA[15]);
    float4* dB = (float4*)(dbase + (long)posB * EDIM);
    dB[0] = make_float4(accB[0],  accB[1],  accB[2],  accB[3]);
    dB[1] = make_float4(accB[4],  accB[5],  accB[6],  accB[7]);
    dB[2] = make_float4(accB[8],  accB[9],  accB[10], accB[11]);
    dB[3] = make_float4(accB[12], accB[13], accB[14], accB[15]);
}

// ---------------------------------------------------------------------------
extern "C" void kernel_launch(void* const* d_in, const int* in_sizes, int n_in,
                              void* d_out, int out_size)
{
    const float* x         = (const float*)d_in[0];
    const float* ew        = (const float*)d_in[1];
    const float* eb        = (const float*)d_in[2];
    const float* ind_in_w  = (const float*)d_in[3];
    const float* ind_in_b  = (const float*)d_in[4];
    const float* ind_out_w = (const float*)d_in[5];
    const float* ind_out_b = (const float*)d_in[6];
    const float* ind_res_w = (const float*)d_in[7];
    const float* fc1_w     = (const float*)d_in[8];
    const float* fc1_b     = (const float*)d_in[9];
    const float* fc2_w     = (const float*)d_in[10];
    const float* fc2_b     = (const float*)d_in[11];
    float* out = (float*)d_out;

    scan_a<<<NQUAD * NHEAD * SPLIT, 256>>>(x, ew, eb);
    scan_b<<<NCHAIN, 272>>>();
    scan_c<<<NQUAD * NHEAD * SPLIT, 256>>>(x, ew, eb, ind_out_b, ind_res_w, out);
    mlp_kernel<<<(NBATCH * 3 * (S_LEN / 2)) / 128, 128>>>(
        ind_in_w, ind_in_b, ind_out_w, fc1_w, fc1_b, fc2_w, fc2_b, out);
}